// round 1
// baseline (speedup 1.0000x reference)
#include <cuda_runtime.h>
#include <math.h>

#define Bc 4
#define Tc 2048
#define Cc 768
#define Hc 6
#define Dc 128
#define Mrows (Bc*Tc)

// Scratch (no cudaMalloc allowed)
__device__ float g_Q[Mrows*Cc];
__device__ float g_K[Mrows*Cc];
__device__ float g_V[Mrows*Cc];
__device__ float g_O[Mrows*Cc];

// ---------------------------------------------------------------------------
// SGEMM (NT): C[m][n] = sum_k A[m][k] * B[n][k]
// BM=BN=128, BK=8, 256 threads, 8x8 per thread (4+64 split mapping).
// ---------------------------------------------------------------------------
__global__ __launch_bounds__(256) void sgemm_nt(
    const float* __restrict__ A, const float* __restrict__ B,
    float* __restrict__ C, int M, int N, int K)
{
    __shared__ float As[8][128];
    __shared__ float Bs[8][128];

    const int bm = blockIdx.y * 128;
    const int bn = blockIdx.x * 128;
    const int tid = threadIdx.x;
    const int lr = tid >> 1;          // 0..127 : tile row to load
    const int lc = (tid & 1) * 4;     // 0 or 4 : k offset
    const float* Ap = A + (bm + lr) * K + lc;
    const float* Bp = B + (bn + lr) * K + lc;
    const int tx = tid & 15;
    const int ty = tid >> 4;

    float acc[8][8];
    #pragma unroll
    for (int i = 0; i < 8; i++)
        #pragma unroll
        for (int j = 0; j < 8; j++) acc[i][j] = 0.f;

    for (int k0 = 0; k0 < K; k0 += 8) {
        float4 av = *reinterpret_cast<const float4*>(Ap + k0);
        float4 bv = *reinterpret_cast<const float4*>(Bp + k0);
        As[lc+0][lr] = av.x; As[lc+1][lr] = av.y;
        As[lc+2][lr] = av.z; As[lc+3][lr] = av.w;
        Bs[lc+0][lr] = bv.x; Bs[lc+1][lr] = bv.y;
        Bs[lc+2][lr] = bv.z; Bs[lc+3][lr] = bv.w;
        __syncthreads();

        #pragma unroll
        for (int kk = 0; kk < 8; kk++) {
            float ar[8], br[8];
            float4 t0 = *reinterpret_cast<const float4*>(&As[kk][ty*4]);
            float4 t1 = *reinterpret_cast<const float4*>(&As[kk][ty*4 + 64]);
            ar[0]=t0.x; ar[1]=t0.y; ar[2]=t0.z; ar[3]=t0.w;
            ar[4]=t1.x; ar[5]=t1.y; ar[6]=t1.z; ar[7]=t1.w;
            float4 u0 = *reinterpret_cast<const float4*>(&Bs[kk][tx*4]);
            float4 u1 = *reinterpret_cast<const float4*>(&Bs[kk][tx*4 + 64]);
            br[0]=u0.x; br[1]=u0.y; br[2]=u0.z; br[3]=u0.w;
            br[4]=u1.x; br[5]=u1.y; br[6]=u1.z; br[7]=u1.w;
            #pragma unroll
            for (int i = 0; i < 8; i++)
                #pragma unroll
                for (int j = 0; j < 8; j++)
                    acc[i][j] += ar[i] * br[j];
        }
        __syncthreads();
    }

    #pragma unroll
    for (int i = 0; i < 8; i++) {
        int row = bm + ((i < 4) ? (ty*4 + i) : (64 + ty*4 + i - 4));
        float4 v0 = make_float4(acc[i][0], acc[i][1], acc[i][2], acc[i][3]);
        float4 v1 = make_float4(acc[i][4], acc[i][5], acc[i][6], acc[i][7]);
        *reinterpret_cast<float4*>(&C[row*N + bn + tx*4])      = v0;
        *reinterpret_cast<float4*>(&C[row*N + bn + 64 + tx*4]) = v1;
    }
}

// ---------------------------------------------------------------------------
// Fused RoPE + RMSNorm, in place on Q and K ([B,T,H,D] layout).
// One warp per (b,t,head); warps 0..5 -> Q heads, 6..11 -> K heads.
// ---------------------------------------------------------------------------
__global__ __launch_bounds__(384) void rope_rms(
    float* __restrict__ Q, float* __restrict__ K,
    const float* __restrict__ cosb, const float* __restrict__ sinb)
{
    const int bt   = blockIdx.x;            // 0..B*T-1
    const int t    = bt % Tc;
    const int w    = threadIdx.x >> 5;      // warp 0..11
    const int lane = threadIdx.x & 31;
    float* base = (w < Hc) ? Q : K;
    const int h = (w < Hc) ? w : (w - Hc);
    float* row = base + (bt * Hc + h) * Dc;
    const float* cp = cosb + t * (Dc/2);
    const float* sp = sinb + t * (Dc/2);

    float y1[2], y2[2];
    float ss = 0.f;
    #pragma unroll
    for (int u = 0; u < 2; u++) {
        int i = lane + u*32;
        float x1 = row[i], x2 = row[i + 64];
        float c = cp[i],  s = sp[i];
        y1[u] = x1*c + x2*s;
        y2[u] = x2*c - x1*s;
        ss += y1[u]*y1[u] + y2[u]*y2[u];
    }
    #pragma unroll
    for (int off = 16; off; off >>= 1)
        ss += __shfl_xor_sync(0xffffffffu, ss, off);
    float sc = rsqrtf(ss * (1.f/128.f) + 1e-15f);
    #pragma unroll
    for (int u = 0; u < 2; u++) {
        int i = lane + u*32;
        row[i]      = y1[u] * sc;
        row[i + 64] = y2[u] * sc;
    }
}

// ---------------------------------------------------------------------------
// FP32 flash attention, causal. 64 queries x 64 keys per tile, D=128.
// Threads: 256 as (tx 0..15, ty 0..15). Thread owns rows ty*4+ii,
// S-cols j = tx + 16*jj, O-cols d = tx + 16*dd.
// ---------------------------------------------------------------------------
#define FBQ 64
#define FBK 64
#define QKS 132                 // padded row stride (floats)
#define PSS 68
#define FLASH_SMEM_FLOATS (3*FBQ*QKS + FBQ*PSS)
#define FLASH_SMEM_BYTES  (FLASH_SMEM_FLOATS * 4)

__global__ __launch_bounds__(256, 1) void flash_attn(
    const float* __restrict__ Q, const float* __restrict__ K,
    const float* __restrict__ V, float* __restrict__ O)
{
    extern __shared__ float sm[];
    float* Qs = sm;
    float* Ks = Qs + FBQ*QKS;
    float* Vs = Ks + FBK*QKS;
    float* Ps = Vs + FBK*QKS;

    const int qt = blockIdx.x;
    const int bh = blockIdx.y;
    const int b = bh / Hc, h = bh % Hc;
    const int tid = threadIdx.x;
    const int tx = tid & 15, ty = tid >> 4;
    const int rowstride = Hc * Dc;   // 768

    // Load Q tile (64 rows x 128)
    const float* Qbase = Q + ((b*Tc + qt*FBQ) * Hc + h) * Dc;
    for (int u = tid; u < FBQ*32; u += 256) {
        int r = u >> 5, c4 = u & 31;
        *reinterpret_cast<float4*>(&Qs[r*QKS + c4*4]) =
            *reinterpret_cast<const float4*>(Qbase + r*rowstride + c4*4);
    }

    float m[4], l[4], o[4][8];
    #pragma unroll
    for (int i = 0; i < 4; i++) {
        m[i] = -1e30f; l[i] = 0.f;
        #pragma unroll
        for (int d = 0; d < 8; d++) o[i][d] = 0.f;
    }

    const float sscale = 0.08838834764831845f;  // 1/sqrt(128)

    for (int kt = 0; kt <= qt; kt++) {
        const float* Kbase = K + ((b*Tc + kt*FBK) * Hc + h) * Dc;
        const float* Vbase = V + ((b*Tc + kt*FBK) * Hc + h) * Dc;
        for (int u = tid; u < FBK*32; u += 256) {
            int r = u >> 5, c4 = u & 31;
            *reinterpret_cast<float4*>(&Ks[r*QKS + c4*4]) =
                *reinterpret_cast<const float4*>(Kbase + r*rowstride + c4*4);
            *reinterpret_cast<float4*>(&Vs[r*QKS + c4*4]) =
                *reinterpret_cast<const float4*>(Vbase + r*rowstride + c4*4);
        }
        __syncthreads();

        // S = Q K^T (4x4 per thread)
        float s[4][4];
        #pragma unroll
        for (int i = 0; i < 4; i++)
            #pragma unroll
            for (int j = 0; j < 4; j++) s[i][j] = 0.f;

        for (int k4 = 0; k4 < 32; k4++) {
            float4 a[4], bb[4];
            #pragma unroll
            for (int ii = 0; ii < 4; ii++)
                a[ii] = *reinterpret_cast<const float4*>(&Qs[(ty*4+ii)*QKS + k4*4]);
            #pragma unroll
            for (int jj = 0; jj < 4; jj++)
                bb[jj] = *reinterpret_cast<const float4*>(&Ks[(tx + jj*16)*QKS + k4*4]);
            #pragma unroll
            for (int ii = 0; ii < 4; ii++)
                #pragma unroll
                for (int jj = 0; jj < 4; jj++)
                    s[ii][jj] += a[ii].x*bb[jj].x + a[ii].y*bb[jj].y +
                                 a[ii].z*bb[jj].z + a[ii].w*bb[jj].w;
        }

        // scale + causal mask
        #pragma unroll
        for (int ii = 0; ii < 4; ii++)
            #pragma unroll
            for (int jj = 0; jj < 4; jj++) {
                s[ii][jj] *= sscale;
                if (kt == qt && (tx + jj*16) > (ty*4 + ii)) s[ii][jj] = -1e30f;
            }

        // online softmax (row reductions over 16 tx lanes)
        #pragma unroll
        for (int ii = 0; ii < 4; ii++) {
            float mx = fmaxf(fmaxf(s[ii][0], s[ii][1]), fmaxf(s[ii][2], s[ii][3]));
            #pragma unroll
            for (int off = 8; off; off >>= 1)
                mx = fmaxf(mx, __shfl_xor_sync(0xffffffffu, mx, off, 16));
            float mnew = fmaxf(m[ii], mx);
            float alpha = __expf(m[ii] - mnew);
            m[ii] = mnew;
            float rs = 0.f;
            #pragma unroll
            for (int jj = 0; jj < 4; jj++) {
                float p = __expf(s[ii][jj] - mnew);
                s[ii][jj] = p;
                rs += p;
            }
            #pragma unroll
            for (int off = 8; off; off >>= 1)
                rs += __shfl_xor_sync(0xffffffffu, rs, off, 16);
            l[ii] = l[ii]*alpha + rs;
            #pragma unroll
            for (int d = 0; d < 8; d++) o[ii][d] *= alpha;
            #pragma unroll
            for (int jj = 0; jj < 4; jj++)
                Ps[(ty*4+ii)*PSS + tx + jj*16] = s[ii][jj];
        }
        __syncthreads();

        // O += P V
        for (int j = 0; j < FBK; j++) {
            float vr[8];
            #pragma unroll
            for (int d = 0; d < 8; d++) vr[d] = Vs[j*QKS + tx + d*16];
            #pragma unroll
            for (int ii = 0; ii < 4; ii++) {
                float p = Ps[(ty*4+ii)*PSS + j];
                #pragma unroll
                for (int d = 0; d < 8; d++) o[ii][d] += p * vr[d];
            }
        }
        __syncthreads();
    }

    // epilogue: O / l  -> [B,T,H,D]
    float* Obase = O + ((b*Tc + qt*FBQ) * Hc + h) * Dc;
    #pragma unroll
    for (int ii = 0; ii < 4; ii++) {
        float inv = 1.f / l[ii];
        #pragma unroll
        for (int d = 0; d < 8; d++)
            Obase[(ty*4+ii)*rowstride + tx + d*16] = o[ii][d] * inv;
    }
}

// ---------------------------------------------------------------------------
extern "C" void kernel_launch(void* const* d_in, const int* in_sizes, int n_in,
                              void* d_out, int out_size)
{
    const float* x  = (const float*)d_in[0];
    const float* cs = (const float*)d_in[1];
    const float* sn = (const float*)d_in[2];
    const float* Wq = (const float*)d_in[3];
    const float* Wk = (const float*)d_in[4];
    const float* Wv = (const float*)d_in[5];
    const float* Wo = (const float*)d_in[6];
    float* out = (float*)d_out;

    float *Qp, *Kp, *Vp, *Op;
    cudaGetSymbolAddress((void**)&Qp, g_Q);
    cudaGetSymbolAddress((void**)&Kp, g_K);
    cudaGetSymbolAddress((void**)&Vp, g_V);
    cudaGetSymbolAddress((void**)&Op, g_O);

    cudaFuncSetAttribute(flash_attn,
                         cudaFuncAttributeMaxDynamicSharedMemorySize,
                         FLASH_SMEM_BYTES);

    dim3 gg(Cc/128, Mrows/128);
    sgemm_nt<<<gg, 256>>>(x, Wq, Qp, Mrows, Cc, Cc);
    sgemm_nt<<<gg, 256>>>(x, Wk, Kp, Mrows, Cc, Cc);
    sgemm_nt<<<gg, 256>>>(x, Wv, Vp, Mrows, Cc, Cc);

    rope_rms<<<Mrows, 384>>>(Qp, Kp, cs, sn);

    flash_attn<<<dim3(Tc/FBQ, Bc*Hc), 256, FLASH_SMEM_BYTES>>>(Qp, Kp, Vp, Op);

    sgemm_nt<<<gg, 256>>>(Op, Wo, out, Mrows, Cc, Cc);
}

// round 3
// speedup vs baseline: 1.3079x; 1.3079x over previous
#include <cuda_runtime.h>
#include <cuda_bf16.h>
#include <cstdint>
#include <math.h>

#define Bc 4
#define Tc 2048
#define Cc 768
#define Hc 6
#define Dc 128
#define Mrows (Bc*Tc)

// Scratch (no cudaMalloc allowed)
__device__ float g_Q[Mrows*Cc];
__device__ float g_K[Mrows*Cc];
__device__ float g_V[Mrows*Cc];
__device__ float g_O[Mrows*Cc];

// ---------------------------------------------------------------------------
// bf16 3-pass error-compensated GEMM (NT): C[m][n] = sum_k A[m][k]*B[n][k]
// A = Ahi + Alo, B = Bhi + Blo (bf16 splits). acc += Ahi*Bhi + Ahi*Blo + Alo*Bhi
// BM=128, BN=128, BK=32. 256 threads = 8 warps (wm 0..3 x wn 0..1).
// Warp tile 32x64 => 2 m-tiles x 8 n-tiles of m16n8k16.
// ---------------------------------------------------------------------------
#define SAB 40   // padded bf16 row stride: 20 banks -> conflict-free frag loads

__device__ __forceinline__ uint32_t lds32(const __nv_bfloat16* p) {
    return *reinterpret_cast<const uint32_t*>(p);
}

__device__ __forceinline__ void mma16816(float* c, const uint32_t* a,
                                         uint32_t b0, uint32_t b1) {
    asm volatile(
        "mma.sync.aligned.m16n8k16.row.col.f32.bf16.bf16.f32 "
        "{%0,%1,%2,%3}, {%4,%5,%6,%7}, {%8,%9}, {%0,%1,%2,%3};\n"
        : "+f"(c[0]), "+f"(c[1]), "+f"(c[2]), "+f"(c[3])
        : "r"(a[0]), "r"(a[1]), "r"(a[2]), "r"(a[3]), "r"(b0), "r"(b1));
}

__device__ __forceinline__ uint32_t pack_bf16x2_rn(float f0, float f1) {
    uint32_t r;
    asm("cvt.rn.bf16x2.f32 %0, %1, %2;\n" : "=r"(r) : "f"(f1), "f"(f0));
    return r;
}

__device__ __forceinline__ void store_split(
    __nv_bfloat16* hi, __nv_bfloat16* lo, int row, int k, float4 v)
{
    float f[4] = {v.x, v.y, v.z, v.w};
    __nv_bfloat16* hp = hi + row*SAB + k;
    __nv_bfloat16* lp = lo + row*SAB + k;
    #pragma unroll
    for (int p = 0; p < 2; p++) {
        float f0 = f[2*p], f1 = f[2*p+1];
        uint32_t h0 = __float_as_uint(f0) & 0xFFFF0000u;
        uint32_t h1 = __float_as_uint(f1) & 0xFFFF0000u;
        uint32_t hpair = (h0 >> 16) | h1;        // elem0 low, elem1 high
        float l0 = f0 - __uint_as_float(h0);
        float l1 = f1 - __uint_as_float(h1);
        *reinterpret_cast<uint32_t*>(hp + 2*p) = hpair;
        *reinterpret_cast<uint32_t*>(lp + 2*p) = pack_bf16x2_rn(l0, l1);
    }
}

__global__ __launch_bounds__(256) void gemm_bf16x3(
    const float* __restrict__ A, const float* __restrict__ B,
    float* __restrict__ C, int M, int N, int K)
{
    __shared__ __nv_bfloat16 sAhi[128*SAB], sAlo[128*SAB];
    __shared__ __nv_bfloat16 sBhi[128*SAB], sBlo[128*SAB];

    const int tid  = threadIdx.x;
    const int warp = tid >> 5, lane = tid & 31;
    const int wm = warp >> 1;         // 0..3 -> 32*wm
    const int wn = warp & 1;          // 0..1 -> 64*wn
    const int g  = lane >> 2;         // 0..7
    const int tg = lane & 3;          // 0..3

    const int bm = blockIdx.y * 128;
    const int bn = blockIdx.x * 128;

    const int lrow = tid >> 1;        // 0..127
    const int lk   = (tid & 1) * 16;  // 0 or 16

    const float* Ag = A + (size_t)(bm + lrow) * K + lk;
    const float* Bg = B + (size_t)(bn + lrow) * K + lk;

    float acc[2][8][4];
    #pragma unroll
    for (int i = 0; i < 2; i++)
        #pragma unroll
        for (int j = 0; j < 8; j++)
            #pragma unroll
            for (int r = 0; r < 4; r++) acc[i][j][r] = 0.f;

    float4 ra[4], rb[4];
    #pragma unroll
    for (int v = 0; v < 4; v++) {
        ra[v] = *reinterpret_cast<const float4*>(Ag + v*4);
        rb[v] = *reinterpret_cast<const float4*>(Bg + v*4);
    }

    const int nk = K / 32;
    for (int kc = 0; kc < nk; kc++) {
        #pragma unroll
        for (int v = 0; v < 4; v++) {
            store_split(sAhi, sAlo, lrow, lk + v*4, ra[v]);
            store_split(sBhi, sBlo, lrow, lk + v*4, rb[v]);
        }
        __syncthreads();

        if (kc + 1 < nk) {
            const float* Ap = Ag + (kc+1)*32;
            const float* Bp = Bg + (kc+1)*32;
            #pragma unroll
            for (int v = 0; v < 4; v++) {
                ra[v] = *reinterpret_cast<const float4*>(Ap + v*4);
                rb[v] = *reinterpret_cast<const float4*>(Bp + v*4);
            }
        }

        #pragma unroll
        for (int s = 0; s < 2; s++) {
            const int kb = s*16 + 2*tg;     // bf16 col index in tile
            uint32_t ahi[2][4], alo[2][4];
            #pragma unroll
            for (int i = 0; i < 2; i++) {
                const int r0 = wm*32 + i*16 + g;
                ahi[i][0] = lds32(&sAhi[ r0     *SAB + kb    ]);
                ahi[i][1] = lds32(&sAhi[(r0+8) *SAB + kb    ]);
                ahi[i][2] = lds32(&sAhi[ r0     *SAB + kb + 8]);
                ahi[i][3] = lds32(&sAhi[(r0+8) *SAB + kb + 8]);
                alo[i][0] = lds32(&sAlo[ r0     *SAB + kb    ]);
                alo[i][1] = lds32(&sAlo[(r0+8) *SAB + kb    ]);
                alo[i][2] = lds32(&sAlo[ r0     *SAB + kb + 8]);
                alo[i][3] = lds32(&sAlo[(r0+8) *SAB + kb + 8]);
            }
            #pragma unroll
            for (int j = 0; j < 8; j++) {
                const int nr = wn*64 + j*8 + g;
                uint32_t bh0 = lds32(&sBhi[nr*SAB + kb    ]);
                uint32_t bh1 = lds32(&sBhi[nr*SAB + kb + 8]);
                uint32_t bl0 = lds32(&sBlo[nr*SAB + kb    ]);
                uint32_t bl1 = lds32(&sBlo[nr*SAB + kb + 8]);
                #pragma unroll
                for (int i = 0; i < 2; i++) {
                    mma16816(acc[i][j], ahi[i], bh0, bh1);
                    mma16816(acc[i][j], ahi[i], bl0, bl1);
                    mma16816(acc[i][j], alo[i], bh0, bh1);
                }
            }
        }
        __syncthreads();
    }

    // epilogue
    #pragma unroll
    for (int i = 0; i < 2; i++) {
        const int r0 = bm + wm*32 + i*16 + g;
        #pragma unroll
        for (int j = 0; j < 8; j++) {
            const int col = bn + wn*64 + j*8 + 2*tg;
            *reinterpret_cast<float2*>(&C[(size_t)r0*N + col]) =
                make_float2(acc[i][j][0], acc[i][j][1]);
            *reinterpret_cast<float2*>(&C[(size_t)(r0+8)*N + col]) =
                make_float2(acc[i][j][2], acc[i][j][3]);
        }
    }
}

// ---------------------------------------------------------------------------
// Fused RoPE + RMSNorm, in place on Q and K ([B,T,H,D] layout).
// ---------------------------------------------------------------------------
__global__ __launch_bounds__(384) void rope_rms(
    float* __restrict__ Q, float* __restrict__ K,
    const float* __restrict__ cosb, const float* __restrict__ sinb)
{
    const int bt   = blockIdx.x;
    const int t    = bt % Tc;
    const int w    = threadIdx.x >> 5;
    const int lane = threadIdx.x & 31;
    float* base = (w < Hc) ? Q : K;
    const int h = (w < Hc) ? w : (w - Hc);
    float* row = base + (bt * Hc + h) * Dc;
    const float* cp = cosb + t * (Dc/2);
    const float* sp = sinb + t * (Dc/2);

    float y1[2], y2[2];
    float ss = 0.f;
    #pragma unroll
    for (int u = 0; u < 2; u++) {
        int i = lane + u*32;
        float x1 = row[i], x2 = row[i + 64];
        float c = cp[i],  s = sp[i];
        y1[u] = x1*c + x2*s;
        y2[u] = x2*c - x1*s;
        ss += y1[u]*y1[u] + y2[u]*y2[u];
    }
    #pragma unroll
    for (int off = 16; off; off >>= 1)
        ss += __shfl_xor_sync(0xffffffffu, ss, off);
    float sc = rsqrtf(ss * (1.f/128.f) + 1e-15f);
    #pragma unroll
    for (int u = 0; u < 2; u++) {
        int i = lane + u*32;
        row[i]      = y1[u] * sc;
        row[i + 64] = y2[u] * sc;
    }
}

// ---------------------------------------------------------------------------
// FP32 flash attention, causal. 64x64 tiles, D=128. (unchanged this round)
// ---------------------------------------------------------------------------
#define FBQ 64
#define FBK 64
#define QKS 132
#define PSS 68
#define FLASH_SMEM_FLOATS (3*FBQ*QKS + FBQ*PSS)
#define FLASH_SMEM_BYTES  (FLASH_SMEM_FLOATS * 4)

__global__ __launch_bounds__(256, 1) void flash_attn(
    const float* __restrict__ Q, const float* __restrict__ K,
    const float* __restrict__ V, float* __restrict__ O)
{
    extern __shared__ float sm[];
    float* Qs = sm;
    float* Ks = Qs + FBQ*QKS;
    float* Vs = Ks + FBK*QKS;
    float* Ps = Vs + FBK*QKS;

    const int qt = blockIdx.x;
    const int bh = blockIdx.y;
    const int b = bh / Hc, h = bh % Hc;
    const int tid = threadIdx.x;
    const int tx = tid & 15, ty = tid >> 4;
    const int rowstride = Hc * Dc;

    const float* Qbase = Q + ((b*Tc + qt*FBQ) * Hc + h) * Dc;
    for (int u = tid; u < FBQ*32; u += 256) {
        int r = u >> 5, c4 = u & 31;
        *reinterpret_cast<float4*>(&Qs[r*QKS + c4*4]) =
            *reinterpret_cast<const float4*>(Qbase + r*rowstride + c4*4);
    }

    float m[4], l[4], o[4][8];
    #pragma unroll
    for (int i = 0; i < 4; i++) {
        m[i] = -1e30f; l[i] = 0.f;
        #pragma unroll
        for (int d = 0; d < 8; d++) o[i][d] = 0.f;
    }

    const float sscale = 0.08838834764831845f;

    for (int kt = 0; kt <= qt; kt++) {
        const float* Kbase = K + ((b*Tc + kt*FBK) * Hc + h) * Dc;
        const float* Vbase = V + ((b*Tc + kt*FBK) * Hc + h) * Dc;
        for (int u = tid; u < FBK*32; u += 256) {
            int r = u >> 5, c4 = u & 31;
            *reinterpret_cast<float4*>(&Ks[r*QKS + c4*4]) =
                *reinterpret_cast<const float4*>(Kbase + r*rowstride + c4*4);
            *reinterpret_cast<float4*>(&Vs[r*QKS + c4*4]) =
                *reinterpret_cast<const float4*>(Vbase + r*rowstride + c4*4);
        }
        __syncthreads();

        float s[4][4];
        #pragma unroll
        for (int i = 0; i < 4; i++)
            #pragma unroll
            for (int j = 0; j < 4; j++) s[i][j] = 0.f;

        for (int k4 = 0; k4 < 32; k4++) {
            float4 a[4], bb[4];
            #pragma unroll
            for (int ii = 0; ii < 4; ii++)
                a[ii] = *reinterpret_cast<const float4*>(&Qs[(ty*4+ii)*QKS + k4*4]);
            #pragma unroll
            for (int jj = 0; jj < 4; jj++)
                bb[jj] = *reinterpret_cast<const float4*>(&Ks[(tx + jj*16)*QKS + k4*4]);
            #pragma unroll
            for (int ii = 0; ii < 4; ii++)
                #pragma unroll
                for (int jj = 0; jj < 4; jj++)
                    s[ii][jj] += a[ii].x*bb[jj].x + a[ii].y*bb[jj].y +
                                 a[ii].z*bb[jj].z + a[ii].w*bb[jj].w;
        }

        #pragma unroll
        for (int ii = 0; ii < 4; ii++)
            #pragma unroll
            for (int jj = 0; jj < 4; jj++) {
                s[ii][jj] *= sscale;
                if (kt == qt && (tx + jj*16) > (ty*4 + ii)) s[ii][jj] = -1e30f;
            }

        #pragma unroll
        for (int ii = 0; ii < 4; ii++) {
            float mx = fmaxf(fmaxf(s[ii][0], s[ii][1]), fmaxf(s[ii][2], s[ii][3]));
            #pragma unroll
            for (int off = 8; off; off >>= 1)
                mx = fmaxf(mx, __shfl_xor_sync(0xffffffffu, mx, off, 16));
            float mnew = fmaxf(m[ii], mx);
            float alpha = __expf(m[ii] - mnew);
            m[ii] = mnew;
            float rs = 0.f;
            #pragma unroll
            for (int jj = 0; jj < 4; jj++) {
                float p = __expf(s[ii][jj] - mnew);
                s[ii][jj] = p;
                rs += p;
            }
            #pragma unroll
            for (int off = 8; off; off >>= 1)
                rs += __shfl_xor_sync(0xffffffffu, rs, off, 16);
            l[ii] = l[ii]*alpha + rs;
            #pragma unroll
            for (int d = 0; d < 8; d++) o[ii][d] *= alpha;
            #pragma unroll
            for (int jj = 0; jj < 4; jj++)
                Ps[(ty*4+ii)*PSS + tx + jj*16] = s[ii][jj];
        }
        __syncthreads();

        for (int j = 0; j < FBK; j++) {
            float vr[8];
            #pragma unroll
            for (int d = 0; d < 8; d++) vr[d] = Vs[j*QKS + tx + d*16];
            #pragma unroll
            for (int ii = 0; ii < 4; ii++) {
                float p = Ps[(ty*4+ii)*PSS + j];
                #pragma unroll
                for (int d = 0; d < 8; d++) o[ii][d] += p * vr[d];
            }
        }
        __syncthreads();
    }

    float* Obase = O + ((b*Tc + qt*FBQ) * Hc + h) * Dc;
    #pragma unroll
    for (int ii = 0; ii < 4; ii++) {
        float inv = 1.f / l[ii];
        #pragma unroll
        for (int d = 0; d < 8; d++)
            Obase[(ty*4+ii)*rowstride + tx + d*16] = o[ii][d] * inv;
    }
}

// ---------------------------------------------------------------------------
extern "C" void kernel_launch(void* const* d_in, const int* in_sizes, int n_in,
                              void* d_out, int out_size)
{
    const float* x  = (const float*)d_in[0];
    const float* cs = (const float*)d_in[1];
    const float* sn = (const float*)d_in[2];
    const float* Wq = (const float*)d_in[3];
    const float* Wk = (const float*)d_in[4];
    const float* Wv = (const float*)d_in[5];
    const float* Wo = (const float*)d_in[6];
    float* out = (float*)d_out;

    float *Qp, *Kp, *Vp, *Op;
    cudaGetSymbolAddress((void**)&Qp, g_Q);
    cudaGetSymbolAddress((void**)&Kp, g_K);
    cudaGetSymbolAddress((void**)&Vp, g_V);
    cudaGetSymbolAddress((void**)&Op, g_O);

    cudaFuncSetAttribute(flash_attn,
                         cudaFuncAttributeMaxDynamicSharedMemorySize,
                         FLASH_SMEM_BYTES);

    dim3 gg(Cc/128, Mrows/128);
    gemm_bf16x3<<<gg, 256>>>(x, Wq, Qp, Mrows, Cc, Cc);
    gemm_bf16x3<<<gg, 256>>>(x, Wk, Kp, Mrows, Cc, Cc);
    gemm_bf16x3<<<gg, 256>>>(x, Wv, Vp, Mrows, Cc, Cc);

    rope_rms<<<Mrows, 384>>>(Qp, Kp, cs, sn);

    flash_attn<<<dim3(Tc/FBQ, Bc*Hc), 256, FLASH_SMEM_BYTES>>>(Qp, Kp, Vp, Op);

    gemm_bf16x3<<<gg, 256>>>(Op, Wo, out, Mrows, Cc, Cc);
}

// round 4
// speedup vs baseline: 2.1294x; 1.6281x over previous
#include <cuda_runtime.h>
#include <cuda_bf16.h>
#include <cstdint>
#include <math.h>

#define Bc 4
#define Tc 2048
#define Cc 768
#define Hc 6
#define Dc 128
#define Mrows (Bc*Tc)

// Scratch (no cudaMalloc allowed)
__device__ float g_Q[Mrows*Cc];
__device__ float g_K[Mrows*Cc];
__device__ float g_V[Mrows*Cc];
__device__ float g_O[Mrows*Cc];

// ---------------------------------------------------------------------------
// common helpers
// ---------------------------------------------------------------------------
__device__ __forceinline__ uint32_t lds32(const __nv_bfloat16* p) {
    return *reinterpret_cast<const uint32_t*>(p);
}

__device__ __forceinline__ void mma16816(float* c, const uint32_t* a,
                                         uint32_t b0, uint32_t b1) {
    asm volatile(
        "mma.sync.aligned.m16n8k16.row.col.f32.bf16.bf16.f32 "
        "{%0,%1,%2,%3}, {%4,%5,%6,%7}, {%8,%9}, {%0,%1,%2,%3};\n"
        : "+f"(c[0]), "+f"(c[1]), "+f"(c[2]), "+f"(c[3])
        : "r"(a[0]), "r"(a[1]), "r"(a[2]), "r"(a[3]), "r"(b0), "r"(b1));
}

__device__ __forceinline__ uint32_t pack_bf16x2_rn(float f0, float f1) {
    uint32_t r;
    asm("cvt.rn.bf16x2.f32 %0, %1, %2;\n" : "=r"(r) : "f"(f1), "f"(f0));
    return r;
}

__device__ __forceinline__ uint32_t cvta_s(const void* p) {
    return (uint32_t)__cvta_generic_to_shared(p);
}

__device__ __forceinline__ void ldsm4(uint32_t* r, uint32_t a) {
    asm volatile("ldmatrix.sync.aligned.m8n8.x4.shared.b16 {%0,%1,%2,%3}, [%4];"
        : "=r"(r[0]), "=r"(r[1]), "=r"(r[2]), "=r"(r[3]) : "r"(a));
}

__device__ __forceinline__ void ldsm4t(uint32_t* r, uint32_t a) {
    asm volatile("ldmatrix.sync.aligned.m8n8.x4.trans.shared.b16 {%0,%1,%2,%3}, [%4];"
        : "=r"(r[0]), "=r"(r[1]), "=r"(r[2]), "=r"(r[3]) : "r"(a));
}

__device__ __forceinline__ float ex2(float x) {
    float y;
    asm("ex2.approx.ftz.f32 %0, %1;" : "=f"(y) : "f"(x));
    return y;
}

// split a float4 into bf16 hi/lo at element offset idx (contiguous 4 elems)
__device__ __forceinline__ void split4(
    __nv_bfloat16* hi, __nv_bfloat16* lo, int idx, float4 v)
{
    float f[4] = {v.x, v.y, v.z, v.w};
    #pragma unroll
    for (int p = 0; p < 2; p++) {
        float f0 = f[2*p], f1 = f[2*p+1];
        uint32_t h0 = __float_as_uint(f0) & 0xFFFF0000u;
        uint32_t h1 = __float_as_uint(f1) & 0xFFFF0000u;
        uint32_t hpair = (h0 >> 16) | h1;
        float l0 = f0 - __uint_as_float(h0);
        float l1 = f1 - __uint_as_float(h1);
        *reinterpret_cast<uint32_t*>(hi + idx + 2*p) = hpair;
        *reinterpret_cast<uint32_t*>(lo + idx + 2*p) = pack_bf16x2_rn(l0, l1);
    }
}

// ---------------------------------------------------------------------------
// bf16 3-pass error-compensated GEMM (NT) — unchanged from R3
// ---------------------------------------------------------------------------
#define SAB 40

__global__ __launch_bounds__(256) void gemm_bf16x3(
    const float* __restrict__ A, const float* __restrict__ B,
    float* __restrict__ C, int M, int N, int K)
{
    __shared__ __nv_bfloat16 sAhi[128*SAB], sAlo[128*SAB];
    __shared__ __nv_bfloat16 sBhi[128*SAB], sBlo[128*SAB];

    const int tid  = threadIdx.x;
    const int warp = tid >> 5, lane = tid & 31;
    const int wm = warp >> 1;
    const int wn = warp & 1;
    const int g  = lane >> 2;
    const int tg = lane & 3;

    const int bm = blockIdx.y * 128;
    const int bn = blockIdx.x * 128;

    const int lrow = tid >> 1;
    const int lk   = (tid & 1) * 16;

    const float* Ag = A + (size_t)(bm + lrow) * K + lk;
    const float* Bg = B + (size_t)(bn + lrow) * K + lk;

    float acc[2][8][4];
    #pragma unroll
    for (int i = 0; i < 2; i++)
        #pragma unroll
        for (int j = 0; j < 8; j++)
            #pragma unroll
            for (int r = 0; r < 4; r++) acc[i][j][r] = 0.f;

    float4 ra[4], rb[4];
    #pragma unroll
    for (int v = 0; v < 4; v++) {
        ra[v] = *reinterpret_cast<const float4*>(Ag + v*4);
        rb[v] = *reinterpret_cast<const float4*>(Bg + v*4);
    }

    const int nk = K / 32;
    for (int kc = 0; kc < nk; kc++) {
        #pragma unroll
        for (int v = 0; v < 4; v++) {
            split4(sAhi, sAlo, lrow*SAB + lk + v*4, ra[v]);
            split4(sBhi, sBlo, lrow*SAB + lk + v*4, rb[v]);
        }
        __syncthreads();

        if (kc + 1 < nk) {
            const float* Ap = Ag + (kc+1)*32;
            const float* Bp = Bg + (kc+1)*32;
            #pragma unroll
            for (int v = 0; v < 4; v++) {
                ra[v] = *reinterpret_cast<const float4*>(Ap + v*4);
                rb[v] = *reinterpret_cast<const float4*>(Bp + v*4);
            }
        }

        #pragma unroll
        for (int s = 0; s < 2; s++) {
            const int kb = s*16 + 2*tg;
            uint32_t ahi[2][4], alo[2][4];
            #pragma unroll
            for (int i = 0; i < 2; i++) {
                const int r0 = wm*32 + i*16 + g;
                ahi[i][0] = lds32(&sAhi[ r0     *SAB + kb    ]);
                ahi[i][1] = lds32(&sAhi[(r0+8) *SAB + kb    ]);
                ahi[i][2] = lds32(&sAhi[ r0     *SAB + kb + 8]);
                ahi[i][3] = lds32(&sAhi[(r0+8) *SAB + kb + 8]);
                alo[i][0] = lds32(&sAlo[ r0     *SAB + kb    ]);
                alo[i][1] = lds32(&sAlo[(r0+8) *SAB + kb    ]);
                alo[i][2] = lds32(&sAlo[ r0     *SAB + kb + 8]);
                alo[i][3] = lds32(&sAlo[(r0+8) *SAB + kb + 8]);
            }
            #pragma unroll
            for (int j = 0; j < 8; j++) {
                const int nr = wn*64 + j*8 + g;
                uint32_t bh0 = lds32(&sBhi[nr*SAB + kb    ]);
                uint32_t bh1 = lds32(&sBhi[nr*SAB + kb + 8]);
                uint32_t bl0 = lds32(&sBlo[nr*SAB + kb    ]);
                uint32_t bl1 = lds32(&sBlo[nr*SAB + kb + 8]);
                #pragma unroll
                for (int i = 0; i < 2; i++) {
                    mma16816(acc[i][j], ahi[i], bh0, bh1);
                    mma16816(acc[i][j], ahi[i], bl0, bl1);
                    mma16816(acc[i][j], alo[i], bh0, bh1);
                }
            }
        }
        __syncthreads();
    }

    #pragma unroll
    for (int i = 0; i < 2; i++) {
        const int r0 = bm + wm*32 + i*16 + g;
        #pragma unroll
        for (int j = 0; j < 8; j++) {
            const int col = bn + wn*64 + j*8 + 2*tg;
            *reinterpret_cast<float2*>(&C[(size_t)r0*N + col]) =
                make_float2(acc[i][j][0], acc[i][j][1]);
            *reinterpret_cast<float2*>(&C[(size_t)(r0+8)*N + col]) =
                make_float2(acc[i][j][2], acc[i][j][3]);
        }
    }
}

// ---------------------------------------------------------------------------
// Fused RoPE + RMSNorm (unchanged)
// ---------------------------------------------------------------------------
__global__ __launch_bounds__(384) void rope_rms(
    float* __restrict__ Q, float* __restrict__ K,
    const float* __restrict__ cosb, const float* __restrict__ sinb)
{
    const int bt   = blockIdx.x;
    const int t    = bt % Tc;
    const int w    = threadIdx.x >> 5;
    const int lane = threadIdx.x & 31;
    float* base = (w < Hc) ? Q : K;
    const int h = (w < Hc) ? w : (w - Hc);
    float* row = base + (bt * Hc + h) * Dc;
    const float* cp = cosb + t * (Dc/2);
    const float* sp = sinb + t * (Dc/2);

    float y1[2], y2[2];
    float ss = 0.f;
    #pragma unroll
    for (int u = 0; u < 2; u++) {
        int i = lane + u*32;
        float x1 = row[i], x2 = row[i + 64];
        float c = cp[i],  s = sp[i];
        y1[u] = x1*c + x2*s;
        y2[u] = x2*c - x1*s;
        ss += y1[u]*y1[u] + y2[u]*y2[u];
    }
    #pragma unroll
    for (int off = 16; off; off >>= 1)
        ss += __shfl_xor_sync(0xffffffffu, ss, off);
    float sc = rsqrtf(ss * (1.f/128.f) + 1e-15f);
    #pragma unroll
    for (int u = 0; u < 2; u++) {
        int i = lane + u*32;
        row[i]      = y1[u] * sc;
        row[i + 64] = y2[u] * sc;
    }
}

// ---------------------------------------------------------------------------
// MMA flash attention (causal). Bq=128 (8 warps x m16), Bk=64, D=128.
// 3-pass bf16 compensation on both S=QK^T and O+=PV.
// Q pre-scaled by log2(e)/sqrt(D) so softmax uses ex2 directly.
// ---------------------------------------------------------------------------
#define QS 136              // bf16 row stride (seg stride 17, conflict-free LDSM)
#define FSM_BYTES ((2*128*QS + 4*64*QS) * 2)

__global__ __launch_bounds__(256, 1) void flash_mma(
    const float* __restrict__ Q, const float* __restrict__ K,
    const float* __restrict__ V, float* __restrict__ O)
{
    extern __shared__ __nv_bfloat16 sb[];
    __nv_bfloat16* Qhi = sb;
    __nv_bfloat16* Qlo = Qhi + 128*QS;
    __nv_bfloat16* Khi = Qlo + 128*QS;
    __nv_bfloat16* Klo = Khi + 64*QS;
    __nv_bfloat16* Vhi = Klo + 64*QS;
    __nv_bfloat16* Vlo = Vhi + 64*QS;

    const int qt = (int)gridDim.x - 1 - (int)blockIdx.x;  // heavy tiles first
    const int bh = blockIdx.y;
    const int b = bh / Hc, h = bh % Hc;
    const int tid  = threadIdx.x;
    const int w    = tid >> 5;
    const int lane = tid & 31;
    const int g    = lane >> 2;
    const int tg   = lane & 3;
    const int rowstride = Hc * Dc;   // 768

    const float C2 = 0.12751745f;    // log2(e)/sqrt(128)

    // load+scale+split Q tile (128 x 128)
    const float* Qbase = Q + ((size_t)(b*Tc + qt*128) * Hc + h) * Dc;
    for (int u = tid; u < 128*32; u += 256) {
        int r = u >> 5, c4 = u & 31;
        float4 v = *reinterpret_cast<const float4*>(Qbase + r*rowstride + c4*4);
        v.x *= C2; v.y *= C2; v.z *= C2; v.w *= C2;
        split4(Qhi, Qlo, r*QS + c4*4, v);
    }

    float o[16][4];
    #pragma unroll
    for (int i = 0; i < 16; i++)
        #pragma unroll
        for (int r = 0; r < 4; r++) o[i][r] = 0.f;
    float m0 = -1e30f, m1 = -1e30f, l0 = 0.f, l1 = 0.f;

    // precomputed LDSM lane offsets
    const int q_off  = (w*16 + (lane & 15))*QS + (lane >> 4)*8;
    const int k_offr = ((lane & 7) + (lane >> 4)*8)*QS + ((lane >> 3) & 1)*8;
    const int v_offr = ((lane & 7) + ((lane >> 3) & 1)*8)*QS + (lane >> 4)*8;

    const int nkt = 2*qt + 2;
    for (int kt = 0; kt < nkt; kt++) {
        const float* Kb = K + ((size_t)(b*Tc + kt*64) * Hc + h) * Dc;
        const float* Vb = V + ((size_t)(b*Tc + kt*64) * Hc + h) * Dc;
        __syncthreads();   // previous iteration's reads done (also covers Q on kt=0... Q written pre-loop, first sync below protects)
        for (int u = tid; u < 64*32; u += 256) {
            int r = u >> 5, c4 = u & 31;
            float4 kv = *reinterpret_cast<const float4*>(Kb + r*rowstride + c4*4);
            split4(Khi, Klo, r*QS + c4*4, kv);
            float4 vv = *reinterpret_cast<const float4*>(Vb + r*rowstride + c4*4);
            split4(Vhi, Vlo, r*QS + c4*4, vv);
        }
        __syncthreads();

        // S = Q K^T  (per warp: 16 x 64), 3-pass
        float s[8][4];
        #pragma unroll
        for (int nt = 0; nt < 8; nt++)
            #pragma unroll
            for (int r = 0; r < 4; r++) s[nt][r] = 0.f;

        #pragma unroll
        for (int ks = 0; ks < 8; ks++) {
            uint32_t ah[4], al[4];
            ldsm4(ah, cvta_s(&Qhi[q_off + ks*16]));
            ldsm4(al, cvta_s(&Qlo[q_off + ks*16]));
            #pragma unroll
            for (int nt4 = 0; nt4 < 4; nt4++) {
                uint32_t bh4[4], bl4[4];
                ldsm4(bh4, cvta_s(&Khi[nt4*16*QS + k_offr + ks*16]));
                ldsm4(bl4, cvta_s(&Klo[nt4*16*QS + k_offr + ks*16]));
                mma16816(s[2*nt4],   ah, bh4[0], bh4[1]);
                mma16816(s[2*nt4],   ah, bl4[0], bl4[1]);
                mma16816(s[2*nt4],   al, bh4[0], bh4[1]);
                mma16816(s[2*nt4+1], ah, bh4[2], bh4[3]);
                mma16816(s[2*nt4+1], ah, bl4[2], bl4[3]);
                mma16816(s[2*nt4+1], al, bh4[2], bh4[3]);
            }
        }

        // causal mask on the two diagonal-overlapping tiles
        if (kt >= nkt - 2) {
            const int gq0 = qt*128 + w*16 + g;
            const int gq1 = gq0 + 8;
            #pragma unroll
            for (int nt = 0; nt < 8; nt++) {
                const int gk = kt*64 + nt*8 + 2*tg;
                if (gk     > gq0) s[nt][0] = -1e30f;
                if (gk + 1 > gq0) s[nt][1] = -1e30f;
                if (gk     > gq1) s[nt][2] = -1e30f;
                if (gk + 1 > gq1) s[nt][3] = -1e30f;
            }
        }

        // online softmax (rows g and g+8; reductions across 4-lane quad)
        float mx0 = -1e30f, mx1 = -1e30f;
        #pragma unroll
        for (int nt = 0; nt < 8; nt++) {
            mx0 = fmaxf(mx0, fmaxf(s[nt][0], s[nt][1]));
            mx1 = fmaxf(mx1, fmaxf(s[nt][2], s[nt][3]));
        }
        #pragma unroll
        for (int off = 1; off <= 2; off <<= 1) {
            mx0 = fmaxf(mx0, __shfl_xor_sync(0xffffffffu, mx0, off));
            mx1 = fmaxf(mx1, __shfl_xor_sync(0xffffffffu, mx1, off));
        }
        const float mn0 = fmaxf(m0, mx0);
        const float mn1 = fmaxf(m1, mx1);
        const float a0 = ex2(m0 - mn0);
        const float a1 = ex2(m1 - mn1);
        m0 = mn0; m1 = mn1;

        float rs0 = 0.f, rs1 = 0.f;
        #pragma unroll
        for (int nt = 0; nt < 8; nt++) {
            s[nt][0] = ex2(s[nt][0] - mn0);
            s[nt][1] = ex2(s[nt][1] - mn0);
            s[nt][2] = ex2(s[nt][2] - mn1);
            s[nt][3] = ex2(s[nt][3] - mn1);
            rs0 += s[nt][0] + s[nt][1];
            rs1 += s[nt][2] + s[nt][3];
        }
        #pragma unroll
        for (int off = 1; off <= 2; off <<= 1) {
            rs0 += __shfl_xor_sync(0xffffffffu, rs0, off);
            rs1 += __shfl_xor_sync(0xffffffffu, rs1, off);
        }
        l0 = l0*a0 + rs0;
        l1 = l1*a1 + rs1;
        #pragma unroll
        for (int dt = 0; dt < 16; dt++) {
            o[dt][0] *= a0; o[dt][1] *= a0;
            o[dt][2] *= a1; o[dt][3] *= a1;
        }

        // O += P V  (P from registers; V via ldmatrix.trans), 3-pass
        #pragma unroll
        for (int ks2 = 0; ks2 < 4; ks2++) {
            uint32_t ph[4], pl[4];
            #pragma unroll
            for (int half = 0; half < 2; half++) {   // a0/a1 then a2/a3 pairs
                const float p0 = s[2*ks2 + half][0], p1 = s[2*ks2 + half][1];
                const float p2 = s[2*ks2 + half][2], p3 = s[2*ks2 + half][3];
                uint32_t h0 = __float_as_uint(p0) & 0xFFFF0000u;
                uint32_t h1 = __float_as_uint(p1) & 0xFFFF0000u;
                uint32_t h2 = __float_as_uint(p2) & 0xFFFF0000u;
                uint32_t h3 = __float_as_uint(p3) & 0xFFFF0000u;
                ph[0 + 2*half] = (h0 >> 16) | h1;
                ph[1 + 2*half] = (h2 >> 16) | h3;
                pl[0 + 2*half] = pack_bf16x2_rn(p0 - __uint_as_float(h0),
                                                p1 - __uint_as_float(h1));
                pl[1 + 2*half] = pack_bf16x2_rn(p2 - __uint_as_float(h2),
                                                p3 - __uint_as_float(h3));
            }
            // reorder: a-frag = {row g k-lo, row g+8 k-lo, row g k-hi, row g+8 k-hi}
            uint32_t pha[4] = {ph[0], ph[1], ph[2], ph[3]};
            uint32_t pla[4] = {pl[0], pl[1], pl[2], pl[3]};

            #pragma unroll
            for (int dt4 = 0; dt4 < 8; dt4++) {
                uint32_t vh4[4], vl4[4];
                ldsm4t(vh4, cvta_s(&Vhi[ks2*16*QS + v_offr + dt4*16]));
                ldsm4t(vl4, cvta_s(&Vlo[ks2*16*QS + v_offr + dt4*16]));
                mma16816(o[2*dt4],   pha, vh4[0], vh4[1]);
                mma16816(o[2*dt4],   pha, vl4[0], vl4[1]);
                mma16816(o[2*dt4],   pla, vh4[0], vh4[1]);
                mma16816(o[2*dt4+1], pha, vh4[2], vh4[3]);
                mma16816(o[2*dt4+1], pha, vl4[2], vl4[3]);
                mma16816(o[2*dt4+1], pla, vh4[2], vh4[3]);
            }
        }
    }

    // epilogue: O / l
    const float inv0 = 1.f / l0;
    const float inv1 = 1.f / l1;
    float* Obase = O + ((size_t)(b*Tc + qt*128) * Hc + h) * Dc;
    const int r0 = w*16 + g;
    #pragma unroll
    for (int dt = 0; dt < 16; dt++) {
        const int col = dt*8 + 2*tg;
        *reinterpret_cast<float2*>(Obase + (size_t)r0*rowstride + col) =
            make_float2(o[dt][0]*inv0, o[dt][1]*inv0);
        *reinterpret_cast<float2*>(Obase + (size_t)(r0+8)*rowstride + col) =
            make_float2(o[dt][2]*inv1, o[dt][3]*inv1);
    }
}

// ---------------------------------------------------------------------------
extern "C" void kernel_launch(void* const* d_in, const int* in_sizes, int n_in,
                              void* d_out, int out_size)
{
    const float* x  = (const float*)d_in[0];
    const float* cs = (const float*)d_in[1];
    const float* sn = (const float*)d_in[2];
    const float* Wq = (const float*)d_in[3];
    const float* Wk = (const float*)d_in[4];
    const float* Wv = (const float*)d_in[5];
    const float* Wo = (const float*)d_in[6];
    float* out = (float*)d_out;

    float *Qp, *Kp, *Vp, *Op;
    cudaGetSymbolAddress((void**)&Qp, g_Q);
    cudaGetSymbolAddress((void**)&Kp, g_K);
    cudaGetSymbolAddress((void**)&Vp, g_V);
    cudaGetSymbolAddress((void**)&Op, g_O);

    cudaFuncSetAttribute(flash_mma,
                         cudaFuncAttributeMaxDynamicSharedMemorySize,
                         FSM_BYTES);

    dim3 gg(Cc/128, Mrows/128);
    gemm_bf16x3<<<gg, 256>>>(x, Wq, Qp, Mrows, Cc, Cc);
    gemm_bf16x3<<<gg, 256>>>(x, Wk, Kp, Mrows, Cc, Cc);
    gemm_bf16x3<<<gg, 256>>>(x, Wv, Vp, Mrows, Cc, Cc);

    rope_rms<<<Mrows, 384>>>(Qp, Kp, cs, sn);

    flash_mma<<<dim3(Tc/128, Bc*Hc), 256, FSM_BYTES>>>(Qp, Kp, Vp, Op);

    gemm_bf16x3<<<gg, 256>>>(Op, Wo, out, Mrows, Cc, Cc);
}

// round 5
// speedup vs baseline: 2.4714x; 1.1606x over previous
#include <cuda_runtime.h>
#include <cuda_bf16.h>
#include <cstdint>
#include <math.h>

#define Bc 4
#define Tc 2048
#define Cc 768
#define Hc 6
#define Dc 128
#define Mrows (Bc*Tc)

// fp32 scratch
__device__ float g_Q[Mrows*Cc];
__device__ float g_K[Mrows*Cc];
__device__ float g_V[Mrows*Cc];
__device__ float g_O[Mrows*Cc];
// bf16 split scratch
__device__ __align__(16) __nv_bfloat16 g_xhi[Mrows*Cc];
__device__ __align__(16) __nv_bfloat16 g_xlo[Mrows*Cc];
__device__ __align__(16) __nv_bfloat16 g_whi[4*Cc*Cc];
__device__ __align__(16) __nv_bfloat16 g_wlo[4*Cc*Cc];
__device__ __align__(16) __nv_bfloat16 g_ohi[Mrows*Cc];
__device__ __align__(16) __nv_bfloat16 g_olo[Mrows*Cc];

// ---------------------------------------------------------------------------
// helpers
// ---------------------------------------------------------------------------
__device__ __forceinline__ void mma16816(float* c, const uint32_t* a,
                                         uint32_t b0, uint32_t b1) {
    asm volatile(
        "mma.sync.aligned.m16n8k16.row.col.f32.bf16.bf16.f32 "
        "{%0,%1,%2,%3}, {%4,%5,%6,%7}, {%8,%9}, {%0,%1,%2,%3};\n"
        : "+f"(c[0]), "+f"(c[1]), "+f"(c[2]), "+f"(c[3])
        : "r"(a[0]), "r"(a[1]), "r"(a[2]), "r"(a[3]), "r"(b0), "r"(b1));
}

__device__ __forceinline__ uint32_t pack_bf16x2_rn(float f0, float f1) {
    uint32_t r;
    asm("cvt.rn.bf16x2.f32 %0, %1, %2;\n" : "=r"(r) : "f"(f1), "f"(f0));
    return r;
}

__device__ __forceinline__ uint32_t cvta_s(const void* p) {
    return (uint32_t)__cvta_generic_to_shared(p);
}

__device__ __forceinline__ void ldsm4(uint32_t* r, uint32_t a) {
    asm volatile("ldmatrix.sync.aligned.m8n8.x4.shared.b16 {%0,%1,%2,%3}, [%4];"
        : "=r"(r[0]), "=r"(r[1]), "=r"(r[2]), "=r"(r[3]) : "r"(a));
}

__device__ __forceinline__ void ldsm4t(uint32_t* r, uint32_t a) {
    asm volatile("ldmatrix.sync.aligned.m8n8.x4.trans.shared.b16 {%0,%1,%2,%3}, [%4];"
        : "=r"(r[0]), "=r"(r[1]), "=r"(r[2]), "=r"(r[3]) : "r"(a));
}

__device__ __forceinline__ float ex2(float x) {
    float y;
    asm("ex2.approx.ftz.f32 %0, %1;" : "=f"(y) : "f"(x));
    return y;
}

__device__ __forceinline__ void cp16(uint32_t dst, const void* src) {
    asm volatile("cp.async.cg.shared.global [%0], [%1], 16;\n"
                 :: "r"(dst), "l"(src) : "memory");
}

__device__ __forceinline__ void split4(
    __nv_bfloat16* hi, __nv_bfloat16* lo, int idx, float4 v)
{
    float f[4] = {v.x, v.y, v.z, v.w};
    #pragma unroll
    for (int p = 0; p < 2; p++) {
        float f0 = f[2*p], f1 = f[2*p+1];
        uint32_t h0 = __float_as_uint(f0) & 0xFFFF0000u;
        uint32_t h1 = __float_as_uint(f1) & 0xFFFF0000u;
        uint32_t hpair = (h0 >> 16) | h1;
        float l0 = f0 - __uint_as_float(h0);
        float l1 = f1 - __uint_as_float(h1);
        *reinterpret_cast<uint32_t*>(hi + idx + 2*p) = hpair;
        *reinterpret_cast<uint32_t*>(lo + idx + 2*p) = pack_bf16x2_rn(l0, l1);
    }
}

// ---------------------------------------------------------------------------
// split pass: fp32 -> bf16 (hi, lo)
// ---------------------------------------------------------------------------
__global__ __launch_bounds__(256) void split_f32(
    const float* __restrict__ src, __nv_bfloat16* __restrict__ hi,
    __nv_bfloat16* __restrict__ lo, int n)
{
    int i = (blockIdx.x*256 + threadIdx.x)*4;
    if (i < n)
        split4(hi, lo, i, *reinterpret_cast<const float4*>(src + i));
}

// ---------------------------------------------------------------------------
// pipelined bf16 3-pass GEMM (NT): C[m][n] = sum_k A[m][k]*B[n][k]
// BM=BN=128, BK=32, 3-stage cp.async, ldmatrix fragments.
// ---------------------------------------------------------------------------
#define SAB 40
#define STAGE_B 40960               // bytes per stage
#define GSM_BYTES (3*STAGE_B)

__global__ __launch_bounds__(256, 1) void gemm_pre(
    const __nv_bfloat16* __restrict__ Ahi, const __nv_bfloat16* __restrict__ Alo,
    const __nv_bfloat16* __restrict__ Bhi, const __nv_bfloat16* __restrict__ Blo,
    float* __restrict__ C, int M, int N, int K)
{
    extern __shared__ __nv_bfloat16 gsm[];
    const uint32_t sm0 = cvta_s(gsm);

    const int tid  = threadIdx.x;
    const int warp = tid >> 5, lane = tid & 31;
    const int wm = warp >> 1;          // 0..3
    const int wn = warp & 1;           // 0..1
    const int g  = lane >> 2;
    const int tg = lane & 3;

    const int bm = blockIdx.y * 128;
    const int bn = blockIdx.x * 128;

    const int lrow = tid >> 1;
    const int lk   = (tid & 1) * 16;

    const __nv_bfloat16* pAh = Ahi + (size_t)(bm + lrow)*K + lk;
    const __nv_bfloat16* pAl = Alo + (size_t)(bm + lrow)*K + lk;
    const __nv_bfloat16* pBh = Bhi + (size_t)(bn + lrow)*K + lk;
    const __nv_bfloat16* pBl = Blo + (size_t)(bn + lrow)*K + lk;
    const uint32_t dbase = sm0 + (uint32_t)(lrow*SAB + lk)*2;

    const int nk = K / 32;

    auto issue = [&](int kc) {
        if (kc < nk) {
            const int ko = kc*32;
            const uint32_t d = dbase + (uint32_t)(kc%3)*STAGE_B;
            cp16(d,              pAh + ko);  cp16(d + 16,          pAh + ko + 8);
            cp16(d + 10240,      pAl + ko);  cp16(d + 10240 + 16,  pAl + ko + 8);
            cp16(d + 20480,      pBh + ko);  cp16(d + 20480 + 16,  pBh + ko + 8);
            cp16(d + 30720,      pBl + ko);  cp16(d + 30720 + 16,  pBl + ko + 8);
        }
        asm volatile("cp.async.commit_group;\n" ::: "memory");
    };

    float acc[2][8][4];
    #pragma unroll
    for (int i = 0; i < 2; i++)
        #pragma unroll
        for (int j = 0; j < 8; j++)
            #pragma unroll
            for (int r = 0; r < 4; r++) acc[i][j][r] = 0.f;

    issue(0);
    issue(1);

    const uint32_t aoff = ((wm*32 + (lane & 15))*SAB + (lane >> 4)*8)*2;
    const uint32_t boff = (((lane & 7) + (lane >> 4)*8)*SAB +
                           ((lane >> 3) & 1)*8)*2 + (uint32_t)(wn*64)*SAB*2;

    #pragma unroll 1
    for (int kc = 0; kc < nk; kc++) {
        if (kc == nk - 1)
            asm volatile("cp.async.wait_group 0;\n" ::: "memory");
        else
            asm volatile("cp.async.wait_group 1;\n" ::: "memory");
        __syncthreads();
        issue(kc + 2);

        const uint32_t sb = sm0 + (uint32_t)(kc%3)*STAGE_B;
        #pragma unroll
        for (int ks = 0; ks < 2; ks++) {
            const uint32_t kbb = ks*32;
            uint32_t ah0[4], ah1[4], al0[4], al1[4];
            ldsm4(ah0, sb + aoff + kbb);
            ldsm4(ah1, sb + aoff + 16*SAB*2 + kbb);
            ldsm4(al0, sb + 10240 + aoff + kbb);
            ldsm4(al1, sb + 10240 + aoff + 16*SAB*2 + kbb);
            #pragma unroll
            for (int nt4 = 0; nt4 < 4; nt4++) {
                uint32_t bh4[4], bl4[4];
                const uint32_t bo = boff + (uint32_t)(nt4*16)*SAB*2 + kbb;
                ldsm4(bh4, sb + 20480 + bo);
                ldsm4(bl4, sb + 30720 + bo);
                mma16816(acc[0][2*nt4],   ah0, bh4[0], bh4[1]);
                mma16816(acc[0][2*nt4],   ah0, bl4[0], bl4[1]);
                mma16816(acc[0][2*nt4],   al0, bh4[0], bh4[1]);
                mma16816(acc[0][2*nt4+1], ah0, bh4[2], bh4[3]);
                mma16816(acc[0][2*nt4+1], ah0, bl4[2], bl4[3]);
                mma16816(acc[0][2*nt4+1], al0, bh4[2], bh4[3]);
                mma16816(acc[1][2*nt4],   ah1, bh4[0], bh4[1]);
                mma16816(acc[1][2*nt4],   ah1, bl4[0], bl4[1]);
                mma16816(acc[1][2*nt4],   al1, bh4[0], bh4[1]);
                mma16816(acc[1][2*nt4+1], ah1, bh4[2], bh4[3]);
                mma16816(acc[1][2*nt4+1], ah1, bl4[2], bl4[3]);
                mma16816(acc[1][2*nt4+1], al1, bh4[2], bh4[3]);
            }
        }
    }

    #pragma unroll
    for (int i = 0; i < 2; i++) {
        const int r0 = bm + wm*32 + i*16 + g;
        #pragma unroll
        for (int j = 0; j < 8; j++) {
            const int col = bn + wn*64 + j*8 + 2*tg;
            *reinterpret_cast<float2*>(&C[(size_t)r0*N + col]) =
                make_float2(acc[i][j][0], acc[i][j][1]);
            *reinterpret_cast<float2*>(&C[(size_t)(r0+8)*N + col]) =
                make_float2(acc[i][j][2], acc[i][j][3]);
        }
    }
}

// ---------------------------------------------------------------------------
// Fused RoPE + RMSNorm (unchanged)
// ---------------------------------------------------------------------------
__global__ __launch_bounds__(384) void rope_rms(
    float* __restrict__ Q, float* __restrict__ K,
    const float* __restrict__ cosb, const float* __restrict__ sinb)
{
    const int bt   = blockIdx.x;
    const int t    = bt % Tc;
    const int w    = threadIdx.x >> 5;
    const int lane = threadIdx.x & 31;
    float* base = (w < Hc) ? Q : K;
    const int h = (w < Hc) ? w : (w - Hc);
    float* row = base + (bt * Hc + h) * Dc;
    const float* cp = cosb + t * (Dc/2);
    const float* sp = sinb + t * (Dc/2);

    float y1[2], y2[2];
    float ss = 0.f;
    #pragma unroll
    for (int u = 0; u < 2; u++) {
        int i = lane + u*32;
        float x1 = row[i], x2 = row[i + 64];
        float c = cp[i],  s = sp[i];
        y1[u] = x1*c + x2*s;
        y2[u] = x2*c - x1*s;
        ss += y1[u]*y1[u] + y2[u]*y2[u];
    }
    #pragma unroll
    for (int off = 16; off; off >>= 1)
        ss += __shfl_xor_sync(0xffffffffu, ss, off);
    float sc = rsqrtf(ss * (1.f/128.f) + 1e-15f);
    #pragma unroll
    for (int u = 0; u < 2; u++) {
        int i = lane + u*32;
        row[i]      = y1[u] * sc;
        row[i + 64] = y2[u] * sc;
    }
}

// ---------------------------------------------------------------------------
// MMA flash attention (unchanged from R4)
// ---------------------------------------------------------------------------
#define QS 136
#define FSM_BYTES ((2*128*QS + 4*64*QS) * 2)

__global__ __launch_bounds__(256, 1) void flash_mma(
    const float* __restrict__ Q, const float* __restrict__ K,
    const float* __restrict__ V, float* __restrict__ O)
{
    extern __shared__ __nv_bfloat16 sb[];
    __nv_bfloat16* Qhi = sb;
    __nv_bfloat16* Qlo = Qhi + 128*QS;
    __nv_bfloat16* Khi = Qlo + 128*QS;
    __nv_bfloat16* Klo = Khi + 64*QS;
    __nv_bfloat16* Vhi = Klo + 64*QS;
    __nv_bfloat16* Vlo = Vhi + 64*QS;

    const int qt = (int)gridDim.x - 1 - (int)blockIdx.x;
    const int bh = blockIdx.y;
    const int b = bh / Hc, h = bh % Hc;
    const int tid  = threadIdx.x;
    const int w    = tid >> 5;
    const int lane = tid & 31;
    const int g    = lane >> 2;
    const int tg   = lane & 3;
    const int rowstride = Hc * Dc;

    const float C2 = 0.12751745f;

    const float* Qbase = Q + ((size_t)(b*Tc + qt*128) * Hc + h) * Dc;
    for (int u = tid; u < 128*32; u += 256) {
        int r = u >> 5, c4 = u & 31;
        float4 v = *reinterpret_cast<const float4*>(Qbase + r*rowstride + c4*4);
        v.x *= C2; v.y *= C2; v.z *= C2; v.w *= C2;
        split4(Qhi, Qlo, r*QS + c4*4, v);
    }

    float o[16][4];
    #pragma unroll
    for (int i = 0; i < 16; i++)
        #pragma unroll
        for (int r = 0; r < 4; r++) o[i][r] = 0.f;
    float m0 = -1e30f, m1 = -1e30f, l0 = 0.f, l1 = 0.f;

    const int q_off  = (w*16 + (lane & 15))*QS + (lane >> 4)*8;
    const int k_offr = ((lane & 7) + (lane >> 4)*8)*QS + ((lane >> 3) & 1)*8;
    const int v_offr = ((lane & 7) + ((lane >> 3) & 1)*8)*QS + (lane >> 4)*8;

    const int nkt = 2*qt + 2;
    for (int kt = 0; kt < nkt; kt++) {
        const float* Kb = K + ((size_t)(b*Tc + kt*64) * Hc + h) * Dc;
        const float* Vb = V + ((size_t)(b*Tc + kt*64) * Hc + h) * Dc;
        __syncthreads();
        for (int u = tid; u < 64*32; u += 256) {
            int r = u >> 5, c4 = u & 31;
            float4 kv = *reinterpret_cast<const float4*>(Kb + r*rowstride + c4*4);
            split4(Khi, Klo, r*QS + c4*4, kv);
            float4 vv = *reinterpret_cast<const float4*>(Vb + r*rowstride + c4*4);
            split4(Vhi, Vlo, r*QS + c4*4, vv);
        }
        __syncthreads();

        float s[8][4];
        #pragma unroll
        for (int nt = 0; nt < 8; nt++)
            #pragma unroll
            for (int r = 0; r < 4; r++) s[nt][r] = 0.f;

        #pragma unroll
        for (int ks = 0; ks < 8; ks++) {
            uint32_t ah[4], al[4];
            ldsm4(ah, cvta_s(&Qhi[q_off + ks*16]));
            ldsm4(al, cvta_s(&Qlo[q_off + ks*16]));
            #pragma unroll
            for (int nt4 = 0; nt4 < 4; nt4++) {
                uint32_t bh4[4], bl4[4];
                ldsm4(bh4, cvta_s(&Khi[nt4*16*QS + k_offr + ks*16]));
                ldsm4(bl4, cvta_s(&Klo[nt4*16*QS + k_offr + ks*16]));
                mma16816(s[2*nt4],   ah, bh4[0], bh4[1]);
                mma16816(s[2*nt4],   ah, bl4[0], bl4[1]);
                mma16816(s[2*nt4],   al, bh4[0], bh4[1]);
                mma16816(s[2*nt4+1], ah, bh4[2], bh4[3]);
                mma16816(s[2*nt4+1], ah, bl4[2], bl4[3]);
                mma16816(s[2*nt4+1], al, bh4[2], bh4[3]);
            }
        }

        if (kt >= nkt - 2) {
            const int gq0 = qt*128 + w*16 + g;
            const int gq1 = gq0 + 8;
            #pragma unroll
            for (int nt = 0; nt < 8; nt++) {
                const int gk = kt*64 + nt*8 + 2*tg;
                if (gk     > gq0) s[nt][0] = -1e30f;
                if (gk + 1 > gq0) s[nt][1] = -1e30f;
                if (gk     > gq1) s[nt][2] = -1e30f;
                if (gk + 1 > gq1) s[nt][3] = -1e30f;
            }
        }

        float mx0 = -1e30f, mx1 = -1e30f;
        #pragma unroll
        for (int nt = 0; nt < 8; nt++) {
            mx0 = fmaxf(mx0, fmaxf(s[nt][0], s[nt][1]));
            mx1 = fmaxf(mx1, fmaxf(s[nt][2], s[nt][3]));
        }
        #pragma unroll
        for (int off = 1; off <= 2; off <<= 1) {
            mx0 = fmaxf(mx0, __shfl_xor_sync(0xffffffffu, mx0, off));
            mx1 = fmaxf(mx1, __shfl_xor_sync(0xffffffffu, mx1, off));
        }
        const float mn0 = fmaxf(m0, mx0);
        const float mn1 = fmaxf(m1, mx1);
        const float a0 = ex2(m0 - mn0);
        const float a1 = ex2(m1 - mn1);
        m0 = mn0; m1 = mn1;

        float rs0 = 0.f, rs1 = 0.f;
        #pragma unroll
        for (int nt = 0; nt < 8; nt++) {
            s[nt][0] = ex2(s[nt][0] - mn0);
            s[nt][1] = ex2(s[nt][1] - mn0);
            s[nt][2] = ex2(s[nt][2] - mn1);
            s[nt][3] = ex2(s[nt][3] - mn1);
            rs0 += s[nt][0] + s[nt][1];
            rs1 += s[nt][2] + s[nt][3];
        }
        #pragma unroll
        for (int off = 1; off <= 2; off <<= 1) {
            rs0 += __shfl_xor_sync(0xffffffffu, rs0, off);
            rs1 += __shfl_xor_sync(0xffffffffu, rs1, off);
        }
        l0 = l0*a0 + rs0;
        l1 = l1*a1 + rs1;
        #pragma unroll
        for (int dt = 0; dt < 16; dt++) {
            o[dt][0] *= a0; o[dt][1] *= a0;
            o[dt][2] *= a1; o[dt][3] *= a1;
        }

        #pragma unroll
        for (int ks2 = 0; ks2 < 4; ks2++) {
            uint32_t pha[4], pla[4];
            #pragma unroll
            for (int half = 0; half < 2; half++) {
                const float p0 = s[2*ks2 + half][0], p1 = s[2*ks2 + half][1];
                const float p2 = s[2*ks2 + half][2], p3 = s[2*ks2 + half][3];
                uint32_t h0 = __float_as_uint(p0) & 0xFFFF0000u;
                uint32_t h1 = __float_as_uint(p1) & 0xFFFF0000u;
                uint32_t h2 = __float_as_uint(p2) & 0xFFFF0000u;
                uint32_t h3 = __float_as_uint(p3) & 0xFFFF0000u;
                pha[0 + 2*half] = (h0 >> 16) | h1;
                pha[1 + 2*half] = (h2 >> 16) | h3;
                pla[0 + 2*half] = pack_bf16x2_rn(p0 - __uint_as_float(h0),
                                                 p1 - __uint_as_float(h1));
                pla[1 + 2*half] = pack_bf16x2_rn(p2 - __uint_as_float(h2),
                                                 p3 - __uint_as_float(h3));
            }
            #pragma unroll
            for (int dt4 = 0; dt4 < 8; dt4++) {
                uint32_t vh4[4], vl4[4];
                ldsm4t(vh4, cvta_s(&Vhi[ks2*16*QS + v_offr + dt4*16]));
                ldsm4t(vl4, cvta_s(&Vlo[ks2*16*QS + v_offr + dt4*16]));
                mma16816(o[2*dt4],   pha, vh4[0], vh4[1]);
                mma16816(o[2*dt4],   pha, vl4[0], vl4[1]);
                mma16816(o[2*dt4],   pla, vh4[0], vh4[1]);
                mma16816(o[2*dt4+1], pha, vh4[2], vh4[3]);
                mma16816(o[2*dt4+1], pha, vl4[2], vl4[3]);
                mma16816(o[2*dt4+1], pla, vh4[2], vh4[3]);
            }
        }
    }

    const float inv0 = 1.f / l0;
    const float inv1 = 1.f / l1;
    float* Obase = O + ((size_t)(b*Tc + qt*128) * Hc + h) * Dc;
    const int r0 = w*16 + g;
    #pragma unroll
    for (int dt = 0; dt < 16; dt++) {
        const int col = dt*8 + 2*tg;
        *reinterpret_cast<float2*>(Obase + (size_t)r0*rowstride + col) =
            make_float2(o[dt][0]*inv0, o[dt][1]*inv0);
        *reinterpret_cast<float2*>(Obase + (size_t)(r0+8)*rowstride + col) =
            make_float2(o[dt][2]*inv1, o[dt][3]*inv1);
    }
}

// ---------------------------------------------------------------------------
extern "C" void kernel_launch(void* const* d_in, const int* in_sizes, int n_in,
                              void* d_out, int out_size)
{
    const float* x  = (const float*)d_in[0];
    const float* cs = (const float*)d_in[1];
    const float* sn = (const float*)d_in[2];
    const float* Wq = (const float*)d_in[3];
    const float* Wk = (const float*)d_in[4];
    const float* Wv = (const float*)d_in[5];
    const float* Wo = (const float*)d_in[6];
    float* out = (float*)d_out;

    float *Qp, *Kp, *Vp, *Op;
    cudaGetSymbolAddress((void**)&Qp, g_Q);
    cudaGetSymbolAddress((void**)&Kp, g_K);
    cudaGetSymbolAddress((void**)&Vp, g_V);
    cudaGetSymbolAddress((void**)&Op, g_O);
    __nv_bfloat16 *xh, *xl, *wh, *wl, *oh, *ol;
    cudaGetSymbolAddress((void**)&xh, g_xhi);
    cudaGetSymbolAddress((void**)&xl, g_xlo);
    cudaGetSymbolAddress((void**)&wh, g_whi);
    cudaGetSymbolAddress((void**)&wl, g_wlo);
    cudaGetSymbolAddress((void**)&oh, g_ohi);
    cudaGetSymbolAddress((void**)&ol, g_olo);

    cudaFuncSetAttribute(flash_mma,
                         cudaFuncAttributeMaxDynamicSharedMemorySize, FSM_BYTES);
    cudaFuncSetAttribute(gemm_pre,
                         cudaFuncAttributeMaxDynamicSharedMemorySize, GSM_BYTES);

    const int NX = Mrows*Cc;      // 6291456
    const int NW = Cc*Cc;         // 589824

    split_f32<<<NX/4/256, 256>>>(x,  xh, xl, NX);
    split_f32<<<NW/4/256, 256>>>(Wq, wh + 0*NW, wl + 0*NW, NW);
    split_f32<<<NW/4/256, 256>>>(Wk, wh + 1*NW, wl + 1*NW, NW);
    split_f32<<<NW/4/256, 256>>>(Wv, wh + 2*NW, wl + 2*NW, NW);
    split_f32<<<NW/4/256, 256>>>(Wo, wh + 3*NW, wl + 3*NW, NW);

    dim3 gg(Cc/128, Mrows/128);
    gemm_pre<<<gg, 256, GSM_BYTES>>>(xh, xl, wh + 0*NW, wl + 0*NW, Qp, Mrows, Cc, Cc);
    gemm_pre<<<gg, 256, GSM_BYTES>>>(xh, xl, wh + 1*NW, wl + 1*NW, Kp, Mrows, Cc, Cc);
    gemm_pre<<<gg, 256, GSM_BYTES>>>(xh, xl, wh + 2*NW, wl + 2*NW, Vp, Mrows, Cc, Cc);

    rope_rms<<<Mrows, 384>>>(Qp, Kp, cs, sn);

    flash_mma<<<dim3(Tc/128, Bc*Hc), 256, FSM_BYTES>>>(Qp, Kp, Vp, Op);

    split_f32<<<NX/4/256, 256>>>(Op, oh, ol, NX);
    gemm_pre<<<gg, 256, GSM_BYTES>>>(oh, ol, wh + 3*NW, wl + 3*NW, out, Mrows, Cc, Cc);
}

// round 6
// speedup vs baseline: 2.7505x; 1.1129x over previous
#include <cuda_runtime.h>
#include <cuda_bf16.h>
#include <cstdint>
#include <math.h>

#define Bc 4
#define Tc 2048
#define Cc 768
#define Hc 6
#define Dc 128
#define Mrows (Bc*Tc)

// fp32 scratch
__device__ float g_Q[Mrows*Cc];
__device__ float g_K[Mrows*Cc];
__device__ float g_V[Mrows*Cc];
// bf16 split scratch
__device__ __align__(16) __nv_bfloat16 g_xhi[Mrows*Cc];
__device__ __align__(16) __nv_bfloat16 g_xlo[Mrows*Cc];
__device__ __align__(16) __nv_bfloat16 g_whi[4*Cc*Cc];
__device__ __align__(16) __nv_bfloat16 g_wlo[4*Cc*Cc];
__device__ __align__(16) __nv_bfloat16 g_qhi[Mrows*Cc];
__device__ __align__(16) __nv_bfloat16 g_qlo[Mrows*Cc];
__device__ __align__(16) __nv_bfloat16 g_khi[Mrows*Cc];
__device__ __align__(16) __nv_bfloat16 g_klo[Mrows*Cc];
__device__ __align__(16) __nv_bfloat16 g_vhi[Mrows*Cc];
__device__ __align__(16) __nv_bfloat16 g_vlo[Mrows*Cc];
__device__ __align__(16) __nv_bfloat16 g_ohi[Mrows*Cc];
__device__ __align__(16) __nv_bfloat16 g_olo[Mrows*Cc];

// ---------------------------------------------------------------------------
// helpers
// ---------------------------------------------------------------------------
__device__ __forceinline__ void mma16816(float* c, const uint32_t* a,
                                         uint32_t b0, uint32_t b1) {
    asm volatile(
        "mma.sync.aligned.m16n8k16.row.col.f32.bf16.bf16.f32 "
        "{%0,%1,%2,%3}, {%4,%5,%6,%7}, {%8,%9}, {%0,%1,%2,%3};\n"
        : "+f"(c[0]), "+f"(c[1]), "+f"(c[2]), "+f"(c[3])
        : "r"(a[0]), "r"(a[1]), "r"(a[2]), "r"(a[3]), "r"(b0), "r"(b1));
}

__device__ __forceinline__ uint32_t pack_bf16x2_rn(float f0, float f1) {
    uint32_t r;
    asm("cvt.rn.bf16x2.f32 %0, %1, %2;\n" : "=r"(r) : "f"(f1), "f"(f0));
    return r;
}

__device__ __forceinline__ uint32_t cvta_s(const void* p) {
    return (uint32_t)__cvta_generic_to_shared(p);
}

__device__ __forceinline__ void ldsm4(uint32_t* r, uint32_t a) {
    asm volatile("ldmatrix.sync.aligned.m8n8.x4.shared.b16 {%0,%1,%2,%3}, [%4];"
        : "=r"(r[0]), "=r"(r[1]), "=r"(r[2]), "=r"(r[3]) : "r"(a));
}

__device__ __forceinline__ void ldsm4t(uint32_t* r, uint32_t a) {
    asm volatile("ldmatrix.sync.aligned.m8n8.x4.trans.shared.b16 {%0,%1,%2,%3}, [%4];"
        : "=r"(r[0]), "=r"(r[1]), "=r"(r[2]), "=r"(r[3]) : "r"(a));
}

__device__ __forceinline__ float ex2(float x) {
    float y;
    asm("ex2.approx.ftz.f32 %0, %1;" : "=f"(y) : "f"(x));
    return y;
}

__device__ __forceinline__ void cp16(uint32_t dst, const void* src) {
    asm volatile("cp.async.cg.shared.global [%0], [%1], 16;\n"
                 :: "r"(dst), "l"(src) : "memory");
}

__device__ __forceinline__ void split_pair(
    float f0, float f1, uint32_t& hp, uint32_t& lp)
{
    uint32_t h0 = __float_as_uint(f0) & 0xFFFF0000u;
    uint32_t h1 = __float_as_uint(f1) & 0xFFFF0000u;
    hp = (h0 >> 16) | h1;
    lp = pack_bf16x2_rn(f0 - __uint_as_float(h0), f1 - __uint_as_float(h1));
}

__device__ __forceinline__ void split4(
    __nv_bfloat16* hi, __nv_bfloat16* lo, int idx, float4 v)
{
    float f[4] = {v.x, v.y, v.z, v.w};
    #pragma unroll
    for (int p = 0; p < 2; p++) {
        uint32_t hp, lp;
        split_pair(f[2*p], f[2*p+1], hp, lp);
        *reinterpret_cast<uint32_t*>(hi + idx + 2*p) = hp;
        *reinterpret_cast<uint32_t*>(lo + idx + 2*p) = lp;
    }
}

// ---------------------------------------------------------------------------
// split pass: fp32 -> bf16 (hi, lo)
// ---------------------------------------------------------------------------
__global__ __launch_bounds__(256) void split_f32(
    const float* __restrict__ src, __nv_bfloat16* __restrict__ hi,
    __nv_bfloat16* __restrict__ lo, int n)
{
    int i = (blockIdx.x*256 + threadIdx.x)*4;
    if (i < n)
        split4(hi, lo, i, *reinterpret_cast<const float4*>(src + i));
}

// ---------------------------------------------------------------------------
// pipelined bf16 3-pass GEMM (NT) — unchanged from R5
// ---------------------------------------------------------------------------
#define SAB 40
#define STAGE_B 40960
#define GSM_BYTES (3*STAGE_B)

__global__ __launch_bounds__(256, 1) void gemm_pre(
    const __nv_bfloat16* __restrict__ Ahi, const __nv_bfloat16* __restrict__ Alo,
    const __nv_bfloat16* __restrict__ Bhi, const __nv_bfloat16* __restrict__ Blo,
    float* __restrict__ C, int M, int N, int K)
{
    extern __shared__ __nv_bfloat16 gsm[];
    const uint32_t sm0 = cvta_s(gsm);

    const int tid  = threadIdx.x;
    const int warp = tid >> 5, lane = tid & 31;
    const int wm = warp >> 1;
    const int wn = warp & 1;
    const int g  = lane >> 2;
    const int tg = lane & 3;

    const int bm = blockIdx.y * 128;
    const int bn = blockIdx.x * 128;

    const int lrow = tid >> 1;
    const int lk   = (tid & 1) * 16;

    const __nv_bfloat16* pAh = Ahi + (size_t)(bm + lrow)*K + lk;
    const __nv_bfloat16* pAl = Alo + (size_t)(bm + lrow)*K + lk;
    const __nv_bfloat16* pBh = Bhi + (size_t)(bn + lrow)*K + lk;
    const __nv_bfloat16* pBl = Blo + (size_t)(bn + lrow)*K + lk;
    const uint32_t dbase = sm0 + (uint32_t)(lrow*SAB + lk)*2;

    const int nk = K / 32;

    auto issue = [&](int kc) {
        if (kc < nk) {
            const int ko = kc*32;
            const uint32_t d = dbase + (uint32_t)(kc%3)*STAGE_B;
            cp16(d,              pAh + ko);  cp16(d + 16,          pAh + ko + 8);
            cp16(d + 10240,      pAl + ko);  cp16(d + 10240 + 16,  pAl + ko + 8);
            cp16(d + 20480,      pBh + ko);  cp16(d + 20480 + 16,  pBh + ko + 8);
            cp16(d + 30720,      pBl + ko);  cp16(d + 30720 + 16,  pBl + ko + 8);
        }
        asm volatile("cp.async.commit_group;\n" ::: "memory");
    };

    float acc[2][8][4];
    #pragma unroll
    for (int i = 0; i < 2; i++)
        #pragma unroll
        for (int j = 0; j < 8; j++)
            #pragma unroll
            for (int r = 0; r < 4; r++) acc[i][j][r] = 0.f;

    issue(0);
    issue(1);

    const uint32_t aoff = ((wm*32 + (lane & 15))*SAB + (lane >> 4)*8)*2;
    const uint32_t boff = (((lane & 7) + (lane >> 4)*8)*SAB +
                           ((lane >> 3) & 1)*8)*2 + (uint32_t)(wn*64)*SAB*2;

    #pragma unroll 1
    for (int kc = 0; kc < nk; kc++) {
        if (kc == nk - 1)
            asm volatile("cp.async.wait_group 0;\n" ::: "memory");
        else
            asm volatile("cp.async.wait_group 1;\n" ::: "memory");
        __syncthreads();
        issue(kc + 2);

        const uint32_t sb = sm0 + (uint32_t)(kc%3)*STAGE_B;
        #pragma unroll
        for (int ks = 0; ks < 2; ks++) {
            const uint32_t kbb = ks*32;
            uint32_t ah0[4], ah1[4], al0[4], al1[4];
            ldsm4(ah0, sb + aoff + kbb);
            ldsm4(ah1, sb + aoff + 16*SAB*2 + kbb);
            ldsm4(al0, sb + 10240 + aoff + kbb);
            ldsm4(al1, sb + 10240 + aoff + 16*SAB*2 + kbb);
            #pragma unroll
            for (int nt4 = 0; nt4 < 4; nt4++) {
                uint32_t bh4[4], bl4[4];
                const uint32_t bo = boff + (uint32_t)(nt4*16)*SAB*2 + kbb;
                ldsm4(bh4, sb + 20480 + bo);
                ldsm4(bl4, sb + 30720 + bo);
                mma16816(acc[0][2*nt4],   ah0, bh4[0], bh4[1]);
                mma16816(acc[0][2*nt4],   ah0, bl4[0], bl4[1]);
                mma16816(acc[0][2*nt4],   al0, bh4[0], bh4[1]);
                mma16816(acc[0][2*nt4+1], ah0, bh4[2], bh4[3]);
                mma16816(acc[0][2*nt4+1], ah0, bl4[2], bl4[3]);
                mma16816(acc[0][2*nt4+1], al0, bh4[2], bh4[3]);
                mma16816(acc[1][2*nt4],   ah1, bh4[0], bh4[1]);
                mma16816(acc[1][2*nt4],   ah1, bl4[0], bl4[1]);
                mma16816(acc[1][2*nt4],   al1, bh4[0], bh4[1]);
                mma16816(acc[1][2*nt4+1], ah1, bh4[2], bh4[3]);
                mma16816(acc[1][2*nt4+1], ah1, bl4[2], bl4[3]);
                mma16816(acc[1][2*nt4+1], al1, bh4[2], bh4[3]);
            }
        }
    }

    #pragma unroll
    for (int i = 0; i < 2; i++) {
        const int r0 = bm + wm*32 + i*16 + g;
        #pragma unroll
        for (int j = 0; j < 8; j++) {
            const int col = bn + wn*64 + j*8 + 2*tg;
            *reinterpret_cast<float2*>(&C[(size_t)r0*N + col]) =
                make_float2(acc[i][j][0], acc[i][j][1]);
            *reinterpret_cast<float2*>(&C[(size_t)(r0+8)*N + col]) =
                make_float2(acc[i][j][2], acc[i][j][3]);
        }
    }
}

// ---------------------------------------------------------------------------
// Fused RoPE + RMSNorm: fp32 Q,K in -> pre-scaled bf16 hi/lo out.
// Q additionally scaled by log2(e)/sqrt(D).
// Lane owns cols {2l, 2l+1, 64+2l, 64+2l+1}.
// ---------------------------------------------------------------------------
__global__ __launch_bounds__(384) void rope_rms_split(
    const float* __restrict__ Q, const float* __restrict__ K,
    const float* __restrict__ cosb, const float* __restrict__ sinb,
    __nv_bfloat16* __restrict__ qhi, __nv_bfloat16* __restrict__ qlo,
    __nv_bfloat16* __restrict__ khi, __nv_bfloat16* __restrict__ klo)
{
    const int bt   = blockIdx.x;
    const int t    = bt % Tc;
    const int w    = threadIdx.x >> 5;
    const int lane = threadIdx.x & 31;
    const bool isQ = (w < Hc);
    const int h = isQ ? w : (w - Hc);
    const size_t roff = ((size_t)bt * Hc + h) * Dc;
    const float* row = (isQ ? Q : K) + roff;
    __nv_bfloat16* ohi = (isQ ? qhi : khi) + roff;
    __nv_bfloat16* olo = (isQ ? qlo : klo) + roff;
    const float* cp = cosb + t * (Dc/2);
    const float* sp = sinb + t * (Dc/2);

    const int j = 2*lane;
    float2 x1 = *reinterpret_cast<const float2*>(row + j);
    float2 x2 = *reinterpret_cast<const float2*>(row + 64 + j);
    float2 cv = *reinterpret_cast<const float2*>(cp + j);
    float2 sv = *reinterpret_cast<const float2*>(sp + j);

    float y1a = x1.x*cv.x + x2.x*sv.x;
    float y1b = x1.y*cv.y + x2.y*sv.y;
    float y2a = x2.x*cv.x - x1.x*sv.x;
    float y2b = x2.y*cv.y - x1.y*sv.y;

    float ss = y1a*y1a + y1b*y1b + y2a*y2a + y2b*y2b;
    #pragma unroll
    for (int off = 16; off; off >>= 1)
        ss += __shfl_xor_sync(0xffffffffu, ss, off);
    float sc = rsqrtf(ss * (1.f/128.f) + 1e-15f);
    if (isQ) sc *= 0.12751745f;        // log2(e)/sqrt(128)

    uint32_t hp, lp;
    split_pair(y1a*sc, y1b*sc, hp, lp);
    *reinterpret_cast<uint32_t*>(ohi + j)      = hp;
    *reinterpret_cast<uint32_t*>(olo + j)      = lp;
    split_pair(y2a*sc, y2b*sc, hp, lp);
    *reinterpret_cast<uint32_t*>(ohi + 64 + j) = hp;
    *reinterpret_cast<uint32_t*>(olo + 64 + j) = lp;
}

// ---------------------------------------------------------------------------
// MMA flash attention (causal), bf16 hi/lo inputs, cp.async 2-stage K/V.
// Bq=128 (8 warps x m16), Bk=64, D=128. 3-pass compensation on S and PV.
// ---------------------------------------------------------------------------
#define QS 136
#define KVT (64*QS)                       // elems per array per stage
#define FSM_BYTES ((2*128*QS + 2*4*KVT) * 2)

__global__ __launch_bounds__(256, 1) void flash_mma(
    const __nv_bfloat16* __restrict__ Qhi_g, const __nv_bfloat16* __restrict__ Qlo_g,
    const __nv_bfloat16* __restrict__ Khi_g, const __nv_bfloat16* __restrict__ Klo_g,
    const __nv_bfloat16* __restrict__ Vhi_g, const __nv_bfloat16* __restrict__ Vlo_g,
    __nv_bfloat16* __restrict__ Ohi_g, __nv_bfloat16* __restrict__ Olo_g)
{
    extern __shared__ __nv_bfloat16 sb[];
    __nv_bfloat16* Qhi = sb;
    __nv_bfloat16* Qlo = Qhi + 128*QS;
    __nv_bfloat16* KVs = Qlo + 128*QS;    // [stage][Khi|Klo|Vhi|Vlo]

    const int qt = (int)gridDim.x - 1 - (int)blockIdx.x;
    const int bh = blockIdx.y;
    const int b = bh / Hc, h = bh % Hc;
    const int tid  = threadIdx.x;
    const int w    = tid >> 5;
    const int lane = tid & 31;
    const int g    = lane >> 2;
    const int tg   = lane & 3;
    const int rowstride = Hc * Dc;        // 768
    const int nkt = 2*qt + 2;

    // Q tile async load (group 0)
    {
        const size_t qoff = ((size_t)(b*Tc + qt*128) * Hc + h) * Dc;
        const __nv_bfloat16* qh = Qhi_g + qoff;
        const __nv_bfloat16* ql = Qlo_g + qoff;
        const uint32_t sQh = cvta_s(Qhi), sQl = cvta_s(Qlo);
        #pragma unroll
        for (int c = 0; c < 8; c++) {
            const int chunk = c*256 + tid;           // 0..2047
            const int r = chunk >> 4, col = (chunk & 15)*8;
            cp16(sQh + (uint32_t)(r*QS + col)*2, qh + r*rowstride + col);
            cp16(sQl + (uint32_t)(r*QS + col)*2, ql + r*rowstride + col);
        }
    }

    auto issueKV = [&](int kt) {
        if (kt < nkt) {
            const size_t koff = ((size_t)(b*Tc + kt*64) * Hc + h) * Dc;
            const uint32_t st = cvta_s(KVs + (kt & 1)*4*KVT);
            const __nv_bfloat16* src[4] = {Khi_g + koff, Klo_g + koff,
                                           Vhi_g + koff, Vlo_g + koff};
            #pragma unroll
            for (int a = 0; a < 4; a++) {
                #pragma unroll
                for (int c = 0; c < 4; c++) {
                    const int chunk = c*256 + tid;   // 0..1023
                    const int r = chunk >> 4, col = (chunk & 15)*8;
                    cp16(st + (uint32_t)(a*KVT + r*QS + col)*2,
                         src[a] + r*rowstride + col);
                }
            }
        }
        asm volatile("cp.async.commit_group;\n" ::: "memory");
    };

    issueKV(0);   // group 0: Q + KV0
    issueKV(1);   // group 1: KV1

    float o[16][4];
    #pragma unroll
    for (int i = 0; i < 16; i++)
        #pragma unroll
        for (int r = 0; r < 4; r++) o[i][r] = 0.f;
    float m0 = -1e30f, m1 = -1e30f, l0 = 0.f, l1 = 0.f;

    const int q_off  = (w*16 + (lane & 15))*QS + (lane >> 4)*8;
    const int k_offr = ((lane & 7) + (lane >> 4)*8)*QS + ((lane >> 3) & 1)*8;
    const int v_offr = ((lane & 7) + ((lane >> 3) & 1)*8)*QS + (lane >> 4)*8;

    #pragma unroll 1
    for (int kt = 0; kt < nkt; kt++) {
        asm volatile("cp.async.wait_group 1;\n" ::: "memory");
        __syncthreads();

        __nv_bfloat16* Khi = KVs + (kt & 1)*4*KVT;
        __nv_bfloat16* Klo = Khi + KVT;
        __nv_bfloat16* Vhi = Klo + KVT;
        __nv_bfloat16* Vlo = Vhi + KVT;

        // S = Q K^T (16 x 64 per warp), 3-pass
        float s[8][4];
        #pragma unroll
        for (int nt = 0; nt < 8; nt++)
            #pragma unroll
            for (int r = 0; r < 4; r++) s[nt][r] = 0.f;

        #pragma unroll
        for (int ks = 0; ks < 8; ks++) {
            uint32_t ah[4], al[4];
            ldsm4(ah, cvta_s(&Qhi[q_off + ks*16]));
            ldsm4(al, cvta_s(&Qlo[q_off + ks*16]));
            #pragma unroll
            for (int nt4 = 0; nt4 < 4; nt4++) {
                uint32_t bh4[4], bl4[4];
                ldsm4(bh4, cvta_s(&Khi[nt4*16*QS + k_offr + ks*16]));
                ldsm4(bl4, cvta_s(&Klo[nt4*16*QS + k_offr + ks*16]));
                mma16816(s[2*nt4],   ah, bh4[0], bh4[1]);
                mma16816(s[2*nt4],   ah, bl4[0], bl4[1]);
                mma16816(s[2*nt4],   al, bh4[0], bh4[1]);
                mma16816(s[2*nt4+1], ah, bh4[2], bh4[3]);
                mma16816(s[2*nt4+1], ah, bl4[2], bl4[3]);
                mma16816(s[2*nt4+1], al, bh4[2], bh4[3]);
            }
        }

        if (kt >= nkt - 2) {
            const int gq0 = qt*128 + w*16 + g;
            const int gq1 = gq0 + 8;
            #pragma unroll
            for (int nt = 0; nt < 8; nt++) {
                const int gk = kt*64 + nt*8 + 2*tg;
                if (gk     > gq0) s[nt][0] = -1e30f;
                if (gk + 1 > gq0) s[nt][1] = -1e30f;
                if (gk     > gq1) s[nt][2] = -1e30f;
                if (gk + 1 > gq1) s[nt][3] = -1e30f;
            }
        }

        float mx0 = -1e30f, mx1 = -1e30f;
        #pragma unroll
        for (int nt = 0; nt < 8; nt++) {
            mx0 = fmaxf(mx0, fmaxf(s[nt][0], s[nt][1]));
            mx1 = fmaxf(mx1, fmaxf(s[nt][2], s[nt][3]));
        }
        #pragma unroll
        for (int off = 1; off <= 2; off <<= 1) {
            mx0 = fmaxf(mx0, __shfl_xor_sync(0xffffffffu, mx0, off));
            mx1 = fmaxf(mx1, __shfl_xor_sync(0xffffffffu, mx1, off));
        }
        const float mn0 = fmaxf(m0, mx0);
        const float mn1 = fmaxf(m1, mx1);
        const float a0 = ex2(m0 - mn0);
        const float a1 = ex2(m1 - mn1);
        m0 = mn0; m1 = mn1;

        float rs0 = 0.f, rs1 = 0.f;
        #pragma unroll
        for (int nt = 0; nt < 8; nt++) {
            s[nt][0] = ex2(s[nt][0] - mn0);
            s[nt][1] = ex2(s[nt][1] - mn0);
            s[nt][2] = ex2(s[nt][2] - mn1);
            s[nt][3] = ex2(s[nt][3] - mn1);
            rs0 += s[nt][0] + s[nt][1];
            rs1 += s[nt][2] + s[nt][3];
        }
        #pragma unroll
        for (int off = 1; off <= 2; off <<= 1) {
            rs0 += __shfl_xor_sync(0xffffffffu, rs0, off);
            rs1 += __shfl_xor_sync(0xffffffffu, rs1, off);
        }
        l0 = l0*a0 + rs0;
        l1 = l1*a1 + rs1;
        #pragma unroll
        for (int dt = 0; dt < 16; dt++) {
            o[dt][0] *= a0; o[dt][1] *= a0;
            o[dt][2] *= a1; o[dt][3] *= a1;
        }

        #pragma unroll
        for (int ks2 = 0; ks2 < 4; ks2++) {
            uint32_t pha[4], pla[4];
            #pragma unroll
            for (int half = 0; half < 2; half++) {
                split_pair(s[2*ks2 + half][0], s[2*ks2 + half][1],
                           pha[0 + 2*half], pla[0 + 2*half]);
                split_pair(s[2*ks2 + half][2], s[2*ks2 + half][3],
                           pha[1 + 2*half], pla[1 + 2*half]);
            }
            #pragma unroll
            for (int dt4 = 0; dt4 < 8; dt4++) {
                uint32_t vh4[4], vl4[4];
                ldsm4t(vh4, cvta_s(&Vhi[ks2*16*QS + v_offr + dt4*16]));
                ldsm4t(vl4, cvta_s(&Vlo[ks2*16*QS + v_offr + dt4*16]));
                mma16816(o[2*dt4],   pha, vh4[0], vh4[1]);
                mma16816(o[2*dt4],   pha, vl4[0], vl4[1]);
                mma16816(o[2*dt4],   pla, vh4[0], vh4[1]);
                mma16816(o[2*dt4+1], pha, vh4[2], vh4[3]);
                mma16816(o[2*dt4+1], pha, vl4[2], vl4[3]);
                mma16816(o[2*dt4+1], pla, vh4[2], vh4[3]);
            }
        }

        __syncthreads();       // all reads of stage kt&1 done
        issueKV(kt + 2);       // refill stage kt&1
    }

    // epilogue: (O / l) -> bf16 hi/lo split
    const float inv0 = 1.f / l0;
    const float inv1 = 1.f / l1;
    const size_t obase = ((size_t)(b*Tc + qt*128) * Hc + h) * Dc;
    const int r0 = w*16 + g;
    #pragma unroll
    for (int dt = 0; dt < 16; dt++) {
        const int col = dt*8 + 2*tg;
        uint32_t hp, lp;
        split_pair(o[dt][0]*inv0, o[dt][1]*inv0, hp, lp);
        *reinterpret_cast<uint32_t*>(Ohi_g + obase + (size_t)r0*rowstride + col) = hp;
        *reinterpret_cast<uint32_t*>(Olo_g + obase + (size_t)r0*rowstride + col) = lp;
        split_pair(o[dt][2]*inv1, o[dt][3]*inv1, hp, lp);
        *reinterpret_cast<uint32_t*>(Ohi_g + obase + (size_t)(r0+8)*rowstride + col) = hp;
        *reinterpret_cast<uint32_t*>(Olo_g + obase + (size_t)(r0+8)*rowstride + col) = lp;
    }
}

// ---------------------------------------------------------------------------
extern "C" void kernel_launch(void* const* d_in, const int* in_sizes, int n_in,
                              void* d_out, int out_size)
{
    const float* x  = (const float*)d_in[0];
    const float* cs = (const float*)d_in[1];
    const float* sn = (const float*)d_in[2];
    const float* Wq = (const float*)d_in[3];
    const float* Wk = (const float*)d_in[4];
    const float* Wv = (const float*)d_in[5];
    const float* Wo = (const float*)d_in[6];
    float* out = (float*)d_out;

    float *Qp, *Kp, *Vp;
    cudaGetSymbolAddress((void**)&Qp, g_Q);
    cudaGetSymbolAddress((void**)&Kp, g_K);
    cudaGetSymbolAddress((void**)&Vp, g_V);
    __nv_bfloat16 *xh, *xl, *wh, *wl, *qh, *ql, *kh, *kl, *vh, *vl, *oh, *ol;
    cudaGetSymbolAddress((void**)&xh, g_xhi);
    cudaGetSymbolAddress((void**)&xl, g_xlo);
    cudaGetSymbolAddress((void**)&wh, g_whi);
    cudaGetSymbolAddress((void**)&wl, g_wlo);
    cudaGetSymbolAddress((void**)&qh, g_qhi);
    cudaGetSymbolAddress((void**)&ql, g_qlo);
    cudaGetSymbolAddress((void**)&kh, g_khi);
    cudaGetSymbolAddress((void**)&kl, g_klo);
    cudaGetSymbolAddress((void**)&vh, g_vhi);
    cudaGetSymbolAddress((void**)&vl, g_vlo);
    cudaGetSymbolAddress((void**)&oh, g_ohi);
    cudaGetSymbolAddress((void**)&ol, g_olo);

    cudaFuncSetAttribute(flash_mma,
                         cudaFuncAttributeMaxDynamicSharedMemorySize, FSM_BYTES);
    cudaFuncSetAttribute(gemm_pre,
                         cudaFuncAttributeMaxDynamicSharedMemorySize, GSM_BYTES);

    const int NX = Mrows*Cc;
    const int NW = Cc*Cc;

    split_f32<<<NX/4/256, 256>>>(x,  xh, xl, NX);
    split_f32<<<NW/4/256, 256>>>(Wq, wh + 0*NW, wl + 0*NW, NW);
    split_f32<<<NW/4/256, 256>>>(Wk, wh + 1*NW, wl + 1*NW, NW);
    split_f32<<<NW/4/256, 256>>>(Wv, wh + 2*NW, wl + 2*NW, NW);
    split_f32<<<NW/4/256, 256>>>(Wo, wh + 3*NW, wl + 3*NW, NW);

    dim3 gg(Cc/128, Mrows/128);
    gemm_pre<<<gg, 256, GSM_BYTES>>>(xh, xl, wh + 0*NW, wl + 0*NW, Qp, Mrows, Cc, Cc);
    gemm_pre<<<gg, 256, GSM_BYTES>>>(xh, xl, wh + 1*NW, wl + 1*NW, Kp, Mrows, Cc, Cc);
    gemm_pre<<<gg, 256, GSM_BYTES>>>(xh, xl, wh + 2*NW, wl + 2*NW, Vp, Mrows, Cc, Cc);

    rope_rms_split<<<Mrows, 384>>>(Qp, Kp, cs, sn, qh, ql, kh, kl);
    split_f32<<<NX/4/256, 256>>>(Vp, vh, vl, NX);

    flash_mma<<<dim3(Tc/128, Bc*Hc), 256, FSM_BYTES>>>(qh, ql, kh, kl, vh, vl, oh, ol);

    gemm_pre<<<gg, 256, GSM_BYTES>>>(oh, ol, wh + 3*NW, wl + 3*NW, out, Mrows, Cc, Cc);
}

// round 9
// speedup vs baseline: 2.7635x; 1.0047x over previous
#include <cuda_runtime.h>
#include <cuda_bf16.h>
#include <cstdint>
#include <math.h>

#define Bc 4
#define Tc 2048
#define Cc 768
#define Hc 6
#define Dc 128
#define Mrows (Bc*Tc)

// fp32 scratch
__device__ float g_Q[Mrows*Cc];
__device__ float g_K[Mrows*Cc];
// bf16 split scratch
__device__ __align__(16) __nv_bfloat16 g_xhi[Mrows*Cc];
__device__ __align__(16) __nv_bfloat16 g_xlo[Mrows*Cc];
__device__ __align__(16) __nv_bfloat16 g_whi[4*Cc*Cc];
__device__ __align__(16) __nv_bfloat16 g_wlo[4*Cc*Cc];
__device__ __align__(16) __nv_bfloat16 g_qhi[Mrows*Cc];
__device__ __align__(16) __nv_bfloat16 g_qlo[Mrows*Cc];
__device__ __align__(16) __nv_bfloat16 g_khi[Mrows*Cc];
__device__ __align__(16) __nv_bfloat16 g_klo[Mrows*Cc];
__device__ __align__(16) __nv_bfloat16 g_vhi[Mrows*Cc];
__device__ __align__(16) __nv_bfloat16 g_vlo[Mrows*Cc];
__device__ __align__(16) __nv_bfloat16 g_ohi[Mrows*Cc];
__device__ __align__(16) __nv_bfloat16 g_olo[Mrows*Cc];

// ---------------------------------------------------------------------------
// helpers
// ---------------------------------------------------------------------------
__device__ __forceinline__ void mma16816(float* c, const uint32_t* a,
                                         uint32_t b0, uint32_t b1) {
    asm volatile(
        "mma.sync.aligned.m16n8k16.row.col.f32.bf16.bf16.f32 "
        "{%0,%1,%2,%3}, {%4,%5,%6,%7}, {%8,%9}, {%0,%1,%2,%3};\n"
        : "+f"(c[0]), "+f"(c[1]), "+f"(c[2]), "+f"(c[3])
        : "r"(a[0]), "r"(a[1]), "r"(a[2]), "r"(a[3]), "r"(b0), "r"(b1));
}

__device__ __forceinline__ uint32_t pack_bf16x2_rn(float f0, float f1) {
    uint32_t r;
    asm("cvt.rn.bf16x2.f32 %0, %1, %2;\n" : "=r"(r) : "f"(f1), "f"(f0));
    return r;
}

__device__ __forceinline__ uint32_t cvta_s(const void* p) {
    return (uint32_t)__cvta_generic_to_shared(p);
}

__device__ __forceinline__ void ldsm4(uint32_t* r, uint32_t a) {
    asm volatile("ldmatrix.sync.aligned.m8n8.x4.shared.b16 {%0,%1,%2,%3}, [%4];"
        : "=r"(r[0]), "=r"(r[1]), "=r"(r[2]), "=r"(r[3]) : "r"(a));
}

__device__ __forceinline__ void ldsm4t(uint32_t* r, uint32_t a) {
    asm volatile("ldmatrix.sync.aligned.m8n8.x4.trans.shared.b16 {%0,%1,%2,%3}, [%4];"
        : "=r"(r[0]), "=r"(r[1]), "=r"(r[2]), "=r"(r[3]) : "r"(a));
}

__device__ __forceinline__ float ex2(float x) {
    float y;
    asm("ex2.approx.ftz.f32 %0, %1;" : "=f"(y) : "f"(x));
    return y;
}

__device__ __forceinline__ void cp16(uint32_t dst, const void* src) {
    asm volatile("cp.async.cg.shared.global [%0], [%1], 16;\n"
                 :: "r"(dst), "l"(src) : "memory");
}

__device__ __forceinline__ void split_pair(
    float f0, float f1, uint32_t& hp, uint32_t& lp)
{
    uint32_t h0 = __float_as_uint(f0) & 0xFFFF0000u;
    uint32_t h1 = __float_as_uint(f1) & 0xFFFF0000u;
    hp = (h0 >> 16) | h1;
    lp = pack_bf16x2_rn(f0 - __uint_as_float(h0), f1 - __uint_as_float(h1));
}

__device__ __forceinline__ void split4(
    __nv_bfloat16* hi, __nv_bfloat16* lo, int idx, float4 v)
{
    float f[4] = {v.x, v.y, v.z, v.w};
    #pragma unroll
    for (int p = 0; p < 2; p++) {
        uint32_t hp, lp;
        split_pair(f[2*p], f[2*p+1], hp, lp);
        *reinterpret_cast<uint32_t*>(hi + idx + 2*p) = hp;
        *reinterpret_cast<uint32_t*>(lo + idx + 2*p) = lp;
    }
}

// ---------------------------------------------------------------------------
// split pass: fp32 -> bf16 (hi, lo)
// ---------------------------------------------------------------------------
__global__ __launch_bounds__(256) void split_f32(
    const float* __restrict__ src, __nv_bfloat16* __restrict__ hi,
    __nv_bfloat16* __restrict__ lo, int n)
{
    int i = (blockIdx.x*256 + threadIdx.x)*4;
    if (i < n)
        split4(hi, lo, i, *reinterpret_cast<const float4*>(src + i));
}

// ---------------------------------------------------------------------------
// pipelined bf16 3-pass GEMM (NT). SPLIT_OUT=true writes bf16 hi/lo directly.
// ---------------------------------------------------------------------------
#define SAB 40
#define STAGE_B 40960
#define GSM_BYTES (3*STAGE_B)

template<bool SPLIT_OUT>
__global__ __launch_bounds__(256, 1) void gemm_pre(
    const __nv_bfloat16* __restrict__ Ahi, const __nv_bfloat16* __restrict__ Alo,
    const __nv_bfloat16* __restrict__ Bhi, const __nv_bfloat16* __restrict__ Blo,
    float* __restrict__ C,
    __nv_bfloat16* __restrict__ Chi, __nv_bfloat16* __restrict__ Clo,
    int M, int N, int K)
{
    extern __shared__ __nv_bfloat16 gsm[];
    const uint32_t sm0 = cvta_s(gsm);

    const int tid  = threadIdx.x;
    const int warp = tid >> 5, lane = tid & 31;
    const int wm = warp >> 1;
    const int wn = warp & 1;
    const int g  = lane >> 2;
    const int tg = lane & 3;

    const int bm = blockIdx.y * 128;
    const int bn = blockIdx.x * 128;

    const int lrow = tid >> 1;
    const int lk   = (tid & 1) * 16;

    const __nv_bfloat16* pAh = Ahi + (size_t)(bm + lrow)*K + lk;
    const __nv_bfloat16* pAl = Alo + (size_t)(bm + lrow)*K + lk;
    const __nv_bfloat16* pBh = Bhi + (size_t)(bn + lrow)*K + lk;
    const __nv_bfloat16* pBl = Blo + (size_t)(bn + lrow)*K + lk;
    const uint32_t dbase = sm0 + (uint32_t)(lrow*SAB + lk)*2;

    const int nk = K / 32;

    auto issue = [&](int kc) {
        if (kc < nk) {
            const int ko = kc*32;
            const uint32_t d = dbase + (uint32_t)(kc%3)*STAGE_B;
            cp16(d,              pAh + ko);  cp16(d + 16,          pAh + ko + 8);
            cp16(d + 10240,      pAl + ko);  cp16(d + 10240 + 16,  pAl + ko + 8);
            cp16(d + 20480,      pBh + ko);  cp16(d + 20480 + 16,  pBh + ko + 8);
            cp16(d + 30720,      pBl + ko);  cp16(d + 30720 + 16,  pBl + ko + 8);
        }
        asm volatile("cp.async.commit_group;\n" ::: "memory");
    };

    float acc[2][8][4];
    #pragma unroll
    for (int i = 0; i < 2; i++)
        #pragma unroll
        for (int j = 0; j < 8; j++)
            #pragma unroll
            for (int r = 0; r < 4; r++) acc[i][j][r] = 0.f;

    issue(0);
    issue(1);

    const uint32_t aoff = ((wm*32 + (lane & 15))*SAB + (lane >> 4)*8)*2;
    const uint32_t boff = (((lane & 7) + (lane >> 4)*8)*SAB +
                           ((lane >> 3) & 1)*8)*2 + (uint32_t)(wn*64)*SAB*2;

    #pragma unroll 1
    for (int kc = 0; kc < nk; kc++) {
        if (kc == nk - 1)
            asm volatile("cp.async.wait_group 0;\n" ::: "memory");
        else
            asm volatile("cp.async.wait_group 1;\n" ::: "memory");
        __syncthreads();
        issue(kc + 2);

        const uint32_t sb = sm0 + (uint32_t)(kc%3)*STAGE_B;
        #pragma unroll
        for (int ks = 0; ks < 2; ks++) {
            const uint32_t kbb = ks*32;
            uint32_t ah0[4], ah1[4], al0[4], al1[4];
            ldsm4(ah0, sb + aoff + kbb);
            ldsm4(ah1, sb + aoff + 16*SAB*2 + kbb);
            ldsm4(al0, sb + 10240 + aoff + kbb);
            ldsm4(al1, sb + 10240 + aoff + 16*SAB*2 + kbb);
            #pragma unroll
            for (int nt4 = 0; nt4 < 4; nt4++) {
                uint32_t bh4[4], bl4[4];
                const uint32_t bo = boff + (uint32_t)(nt4*16)*SAB*2 + kbb;
                ldsm4(bh4, sb + 20480 + bo);
                ldsm4(bl4, sb + 30720 + bo);
                mma16816(acc[0][2*nt4],   ah0, bh4[0], bh4[1]);
                mma16816(acc[0][2*nt4],   ah0, bl4[0], bl4[1]);
                mma16816(acc[0][2*nt4],   al0, bh4[0], bh4[1]);
                mma16816(acc[0][2*nt4+1], ah0, bh4[2], bh4[3]);
                mma16816(acc[0][2*nt4+1], ah0, bl4[2], bl4[3]);
                mma16816(acc[0][2*nt4+1], al0, bh4[2], bh4[3]);
                mma16816(acc[1][2*nt4],   ah1, bh4[0], bh4[1]);
                mma16816(acc[1][2*nt4],   ah1, bl4[0], bl4[1]);
                mma16816(acc[1][2*nt4],   al1, bh4[0], bh4[1]);
                mma16816(acc[1][2*nt4+1], ah1, bh4[2], bh4[3]);
                mma16816(acc[1][2*nt4+1], ah1, bl4[2], bl4[3]);
                mma16816(acc[1][2*nt4+1], al1, bh4[2], bh4[3]);
            }
        }
    }

    #pragma unroll
    for (int i = 0; i < 2; i++) {
        const int r0 = bm + wm*32 + i*16 + g;
        #pragma unroll
        for (int j = 0; j < 8; j++) {
            const int col = bn + wn*64 + j*8 + 2*tg;
            if (SPLIT_OUT) {
                uint32_t hp, lp;
                split_pair(acc[i][j][0], acc[i][j][1], hp, lp);
                *reinterpret_cast<uint32_t*>(Chi + (size_t)r0*N + col) = hp;
                *reinterpret_cast<uint32_t*>(Clo + (size_t)r0*N + col) = lp;
                split_pair(acc[i][j][2], acc[i][j][3], hp, lp);
                *reinterpret_cast<uint32_t*>(Chi + (size_t)(r0+8)*N + col) = hp;
                *reinterpret_cast<uint32_t*>(Clo + (size_t)(r0+8)*N + col) = lp;
            } else {
                *reinterpret_cast<float2*>(&C[(size_t)r0*N + col]) =
                    make_float2(acc[i][j][0], acc[i][j][1]);
                *reinterpret_cast<float2*>(&C[(size_t)(r0+8)*N + col]) =
                    make_float2(acc[i][j][2], acc[i][j][3]);
            }
        }
    }
}

// ---------------------------------------------------------------------------
// Fused RoPE + RMSNorm -> pre-scaled bf16 hi/lo
// ---------------------------------------------------------------------------
__global__ __launch_bounds__(384) void rope_rms_split(
    const float* __restrict__ Q, const float* __restrict__ K,
    const float* __restrict__ cosb, const float* __restrict__ sinb,
    __nv_bfloat16* __restrict__ qhi, __nv_bfloat16* __restrict__ qlo,
    __nv_bfloat16* __restrict__ khi, __nv_bfloat16* __restrict__ klo)
{
    const int bt   = blockIdx.x;
    const int t    = bt % Tc;
    const int w    = threadIdx.x >> 5;
    const int lane = threadIdx.x & 31;
    const bool isQ = (w < Hc);
    const int h = isQ ? w : (w - Hc);
    const size_t roff = ((size_t)bt * Hc + h) * Dc;
    const float* row = (isQ ? Q : K) + roff;
    __nv_bfloat16* ohi = (isQ ? qhi : khi) + roff;
    __nv_bfloat16* olo = (isQ ? qlo : klo) + roff;
    const float* cp = cosb + t * (Dc/2);
    const float* sp = sinb + t * (Dc/2);

    const int j = 2*lane;
    float2 x1 = *reinterpret_cast<const float2*>(row + j);
    float2 x2 = *reinterpret_cast<const float2*>(row + 64 + j);
    float2 cv = *reinterpret_cast<const float2*>(cp + j);
    float2 sv = *reinterpret_cast<const float2*>(sp + j);

    float y1a = x1.x*cv.x + x2.x*sv.x;
    float y1b = x1.y*cv.y + x2.y*sv.y;
    float y2a = x2.x*cv.x - x1.x*sv.x;
    float y2b = x2.y*cv.y - x1.y*sv.y;

    float ss = y1a*y1a + y1b*y1b + y2a*y2a + y2b*y2b;
    #pragma unroll
    for (int off = 16; off; off >>= 1)
        ss += __shfl_xor_sync(0xffffffffu, ss, off);
    float sc = rsqrtf(ss * (1.f/128.f) + 1e-15f);
    if (isQ) sc *= 0.12751745f;        // log2(e)/sqrt(128)

    uint32_t hp, lp;
    split_pair(y1a*sc, y1b*sc, hp, lp);
    *reinterpret_cast<uint32_t*>(ohi + j)      = hp;
    *reinterpret_cast<uint32_t*>(olo + j)      = lp;
    split_pair(y2a*sc, y2b*sc, hp, lp);
    *reinterpret_cast<uint32_t*>(ohi + 64 + j) = hp;
    *reinterpret_cast<uint32_t*>(olo + 64 + j) = lp;
}

// ---------------------------------------------------------------------------
// MMA flash attention (causal). Bq=128, Bk=64, D=128.
// Q frags hoisted to registers; full 3-pass compensation on S and PV (R6 math).
// ---------------------------------------------------------------------------
#define QS 136
#define KVT (64*QS)
#define FSM_BYTES ((2*128*QS + 2*4*KVT) * 2)

__global__ __launch_bounds__(256, 1) void flash_mma(
    const __nv_bfloat16* __restrict__ Qhi_g, const __nv_bfloat16* __restrict__ Qlo_g,
    const __nv_bfloat16* __restrict__ Khi_g, const __nv_bfloat16* __restrict__ Klo_g,
    const __nv_bfloat16* __restrict__ Vhi_g, const __nv_bfloat16* __restrict__ Vlo_g,
    __nv_bfloat16* __restrict__ Ohi_g, __nv_bfloat16* __restrict__ Olo_g)
{
    extern __shared__ __nv_bfloat16 sb[];
    __nv_bfloat16* Qhi = sb;
    __nv_bfloat16* Qlo = Qhi + 128*QS;
    __nv_bfloat16* KVs = Qlo + 128*QS;

    const int qt = (int)gridDim.x - 1 - (int)blockIdx.x;
    const int bh = blockIdx.y;
    const int b = bh / Hc, h = bh % Hc;
    const int tid  = threadIdx.x;
    const int w    = tid >> 5;
    const int lane = tid & 31;
    const int g    = lane >> 2;
    const int tg   = lane & 3;
    const int rowstride = Hc * Dc;
    const int nkt = 2*qt + 2;

    // Q tile async load (part of group 0)
    {
        const size_t qoff = ((size_t)(b*Tc + qt*128) * Hc + h) * Dc;
        const __nv_bfloat16* qhg = Qhi_g + qoff;
        const __nv_bfloat16* qlg = Qlo_g + qoff;
        const uint32_t sQh = cvta_s(Qhi), sQl = cvta_s(Qlo);
        #pragma unroll
        for (int c = 0; c < 8; c++) {
            const int chunk = c*256 + tid;
            const int r = chunk >> 4, col = (chunk & 15)*8;
            cp16(sQh + (uint32_t)(r*QS + col)*2, qhg + r*rowstride + col);
            cp16(sQl + (uint32_t)(r*QS + col)*2, qlg + r*rowstride + col);
        }
    }

    auto issueKV = [&](int kt) {
        if (kt < nkt) {
            const size_t koff = ((size_t)(b*Tc + kt*64) * Hc + h) * Dc;
            const uint32_t st = cvta_s(KVs + (kt & 1)*4*KVT);
            const __nv_bfloat16* src[4] = {Khi_g + koff, Klo_g + koff,
                                           Vhi_g + koff, Vlo_g + koff};
            #pragma unroll
            for (int a = 0; a < 4; a++) {
                #pragma unroll
                for (int c = 0; c < 4; c++) {
                    const int chunk = c*256 + tid;
                    const int r = chunk >> 4, col = (chunk & 15)*8;
                    cp16(st + (uint32_t)(a*KVT + r*QS + col)*2,
                         src[a] + r*rowstride + col);
                }
            }
        }
        asm volatile("cp.async.commit_group;\n" ::: "memory");
    };

    issueKV(0);   // group 0: Q + KV0
    issueKV(1);   // group 1: KV1

    const int q_off  = (w*16 + (lane & 15))*QS + (lane >> 4)*8;
    const int k_offr = ((lane & 7) + (lane >> 4)*8)*QS + ((lane >> 3) & 1)*8;
    const int v_offr = ((lane & 7) + ((lane >> 3) & 1)*8)*QS + (lane >> 4)*8;

    // wait for group 0 (Q + KV0), hoist Q fragments into registers
    asm volatile("cp.async.wait_group 1;\n" ::: "memory");
    __syncthreads();
    uint32_t qfh[8][4], qfl[8][4];
    #pragma unroll
    for (int ks = 0; ks < 8; ks++) {
        ldsm4(qfh[ks], cvta_s(&Qhi[q_off + ks*16]));
        ldsm4(qfl[ks], cvta_s(&Qlo[q_off + ks*16]));
    }

    float o[16][4];
    #pragma unroll
    for (int i = 0; i < 16; i++)
        #pragma unroll
        for (int r = 0; r < 4; r++) o[i][r] = 0.f;
    float m0 = -1e30f, m1 = -1e30f, l0 = 0.f, l1 = 0.f;

    #pragma unroll 1
    for (int kt = 0; kt < nkt; kt++) {
        asm volatile("cp.async.wait_group 1;\n" ::: "memory");
        __syncthreads();

        __nv_bfloat16* Khi = KVs + (kt & 1)*4*KVT;
        __nv_bfloat16* Klo = Khi + KVT;
        __nv_bfloat16* Vhi = Klo + KVT;
        __nv_bfloat16* Vlo = Vhi + KVT;

        // S = Q K^T (16 x 64 per warp), 3-pass
        float s[8][4];
        #pragma unroll
        for (int nt = 0; nt < 8; nt++)
            #pragma unroll
            for (int r = 0; r < 4; r++) s[nt][r] = 0.f;

        #pragma unroll
        for (int ks = 0; ks < 8; ks++) {
            #pragma unroll
            for (int nt4 = 0; nt4 < 4; nt4++) {
                uint32_t bh4[4], bl4[4];
                ldsm4(bh4, cvta_s(&Khi[nt4*16*QS + k_offr + ks*16]));
                ldsm4(bl4, cvta_s(&Klo[nt4*16*QS + k_offr + ks*16]));
                mma16816(s[2*nt4],   qfh[ks], bh4[0], bh4[1]);
                mma16816(s[2*nt4],   qfh[ks], bl4[0], bl4[1]);
                mma16816(s[2*nt4],   qfl[ks], bh4[0], bh4[1]);
                mma16816(s[2*nt4+1], qfh[ks], bh4[2], bh4[3]);
                mma16816(s[2*nt4+1], qfh[ks], bl4[2], bl4[3]);
                mma16816(s[2*nt4+1], qfl[ks], bh4[2], bh4[3]);
            }
        }

        if (kt >= nkt - 2) {
            const int gq0 = qt*128 + w*16 + g;
            const int gq1 = gq0 + 8;
            #pragma unroll
            for (int nt = 0; nt < 8; nt++) {
                const int gk = kt*64 + nt*8 + 2*tg;
                if (gk     > gq0) s[nt][0] = -1e30f;
                if (gk + 1 > gq0) s[nt][1] = -1e30f;
                if (gk     > gq1) s[nt][2] = -1e30f;
                if (gk + 1 > gq1) s[nt][3] = -1e30f;
            }
        }

        float mx0 = -1e30f, mx1 = -1e30f;
        #pragma unroll
        for (int nt = 0; nt < 8; nt++) {
            mx0 = fmaxf(mx0, fmaxf(s[nt][0], s[nt][1]));
            mx1 = fmaxf(mx1, fmaxf(s[nt][2], s[nt][3]));
        }
        #pragma unroll
        for (int off = 1; off <= 2; off <<= 1) {
            mx0 = fmaxf(mx0, __shfl_xor_sync(0xffffffffu, mx0, off));
            mx1 = fmaxf(mx1, __shfl_xor_sync(0xffffffffu, mx1, off));
        }
        const float mn0 = fmaxf(m0, mx0);
        const float mn1 = fmaxf(m1, mx1);
        const float a0 = ex2(m0 - mn0);
        const float a1 = ex2(m1 - mn1);
        m0 = mn0; m1 = mn1;

        float rs0 = 0.f, rs1 = 0.f;
        #pragma unroll
        for (int nt = 0; nt < 8; nt++) {
            s[nt][0] = ex2(s[nt][0] - mn0);
            s[nt][1] = ex2(s[nt][1] - mn0);
            s[nt][2] = ex2(s[nt][2] - mn1);
            s[nt][3] = ex2(s[nt][3] - mn1);
            rs0 += s[nt][0] + s[nt][1];
            rs1 += s[nt][2] + s[nt][3];
        }
        #pragma unroll
        for (int off = 1; off <= 2; off <<= 1) {
            rs0 += __shfl_xor_sync(0xffffffffu, rs0, off);
            rs1 += __shfl_xor_sync(0xffffffffu, rs1, off);
        }
        l0 = l0*a0 + rs0;
        l1 = l1*a1 + rs1;
        #pragma unroll
        for (int dt = 0; dt < 16; dt++) {
            o[dt][0] *= a0; o[dt][1] *= a0;
            o[dt][2] *= a1; o[dt][3] *= a1;
        }

        // O += P V  (P hi/lo split from fp32; 3-pass compensation)
        #pragma unroll
        for (int ks2 = 0; ks2 < 4; ks2++) {
            uint32_t pha[4], pla[4];
            #pragma unroll
            for (int half = 0; half < 2; half++) {
                split_pair(s[2*ks2 + half][0], s[2*ks2 + half][1],
                           pha[0 + 2*half], pla[0 + 2*half]);
                split_pair(s[2*ks2 + half][2], s[2*ks2 + half][3],
                           pha[1 + 2*half], pla[1 + 2*half]);
            }
            #pragma unroll
            for (int dt4 = 0; dt4 < 8; dt4++) {
                uint32_t vh4[4], vl4[4];
                ldsm4t(vh4, cvta_s(&Vhi[ks2*16*QS + v_offr + dt4*16]));
                ldsm4t(vl4, cvta_s(&Vlo[ks2*16*QS + v_offr + dt4*16]));
                mma16816(o[2*dt4],   pha, vh4[0], vh4[1]);
                mma16816(o[2*dt4],   pha, vl4[0], vl4[1]);
                mma16816(o[2*dt4],   pla, vh4[0], vh4[1]);
                mma16816(o[2*dt4+1], pha, vh4[2], vh4[3]);
                mma16816(o[2*dt4+1], pha, vl4[2], vl4[3]);
                mma16816(o[2*dt4+1], pla, vh4[2], vh4[3]);
            }
        }

        __syncthreads();
        issueKV(kt + 2);
    }

    // epilogue: (O / l) -> bf16 hi/lo split
    const float inv0 = 1.f / l0;
    const float inv1 = 1.f / l1;
    const size_t obase = ((size_t)(b*Tc + qt*128) * Hc + h) * Dc;
    const int r0 = w*16 + g;
    #pragma unroll
    for (int dt = 0; dt < 16; dt++) {
        const int col = dt*8 + 2*tg;
        uint32_t hp, lp;
        split_pair(o[dt][0]*inv0, o[dt][1]*inv0, hp, lp);
        *reinterpret_cast<uint32_t*>(Ohi_g + obase + (size_t)r0*rowstride + col) = hp;
        *reinterpret_cast<uint32_t*>(Olo_g + obase + (size_t)r0*rowstride + col) = lp;
        split_pair(o[dt][2]*inv1, o[dt][3]*inv1, hp, lp);
        *reinterpret_cast<uint32_t*>(Ohi_g + obase + (size_t)(r0+8)*rowstride + col) = hp;
        *reinterpret_cast<uint32_t*>(Olo_g + obase + (size_t)(r0+8)*rowstride + col) = lp;
    }
}

// ---------------------------------------------------------------------------
extern "C" void kernel_launch(void* const* d_in, const int* in_sizes, int n_in,
                              void* d_out, int out_size)
{
    const float* x  = (const float*)d_in[0];
    const float* cs = (const float*)d_in[1];
    const float* sn = (const float*)d_in[2];
    const float* Wq = (const float*)d_in[3];
    const float* Wk = (const float*)d_in[4];
    const float* Wv = (const float*)d_in[5];
    const float* Wo = (const float*)d_in[6];
    float* out = (float*)d_out;

    float *Qp, *Kp;
    cudaGetSymbolAddress((void**)&Qp, g_Q);
    cudaGetSymbolAddress((void**)&Kp, g_K);
    __nv_bfloat16 *xh, *xl, *wh, *wl, *qh, *ql, *kh, *kl, *vh, *vl, *oh, *ol;
    cudaGetSymbolAddress((void**)&xh, g_xhi);
    cudaGetSymbolAddress((void**)&xl, g_xlo);
    cudaGetSymbolAddress((void**)&wh, g_whi);
    cudaGetSymbolAddress((void**)&wl, g_wlo);
    cudaGetSymbolAddress((void**)&qh, g_qhi);
    cudaGetSymbolAddress((void**)&ql, g_qlo);
    cudaGetSymbolAddress((void**)&kh, g_khi);
    cudaGetSymbolAddress((void**)&kl, g_klo);
    cudaGetSymbolAddress((void**)&vh, g_vhi);
    cudaGetSymbolAddress((void**)&vl, g_vlo);
    cudaGetSymbolAddress((void**)&oh, g_ohi);
    cudaGetSymbolAddress((void**)&ol, g_olo);

    cudaFuncSetAttribute(flash_mma,
                         cudaFuncAttributeMaxDynamicSharedMemorySize, FSM_BYTES);
    cudaFuncSetAttribute(gemm_pre<false>,
                         cudaFuncAttributeMaxDynamicSharedMemorySize, GSM_BYTES);
    cudaFuncSetAttribute(gemm_pre<true>,
                         cudaFuncAttributeMaxDynamicSharedMemorySize, GSM_BYTES);

    const int NX = Mrows*Cc;
    const int NW = Cc*Cc;

    split_f32<<<NX/4/256, 256>>>(x,  xh, xl, NX);
    split_f32<<<NW/4/256, 256>>>(Wq, wh + 0*NW, wl + 0*NW, NW);
    split_f32<<<NW/4/256, 256>>>(Wk, wh + 1*NW, wl + 1*NW, NW);
    split_f32<<<NW/4/256, 256>>>(Wv, wh + 2*NW, wl + 2*NW, NW);
    split_f32<<<NW/4/256, 256>>>(Wo, wh + 3*NW, wl + 3*NW, NW);

    dim3 gg(Cc/128, Mrows/128);
    gemm_pre<false><<<gg, 256, GSM_BYTES>>>(xh, xl, wh + 0*NW, wl + 0*NW,
                                            Qp, nullptr, nullptr, Mrows, Cc, Cc);
    gemm_pre<false><<<gg, 256, GSM_BYTES>>>(xh, xl, wh + 1*NW, wl + 1*NW,
                                            Kp, nullptr, nullptr, Mrows, Cc, Cc);
    gemm_pre<true><<<gg, 256, GSM_BYTES>>>(xh, xl, wh + 2*NW, wl + 2*NW,
                                           nullptr, vh, vl, Mrows, Cc, Cc);

    rope_rms_split<<<Mrows, 384>>>(Qp, Kp, cs, sn, qh, ql, kh, kl);

    flash_mma<<<dim3(Tc/128, Bc*Hc), 256, FSM_BYTES>>>(qh, ql, kh, kl, vh, vl, oh, ol);

    gemm_pre<false><<<gg, 256, GSM_BYTES>>>(oh, ol, wh + 3*NW, wl + 3*NW,
                                            out, nullptr, nullptr, Mrows, Cc, Cc);
}